// round 7
// baseline (speedup 1.0000x reference)
#include <cuda_runtime.h>
#include <math.h>

#define NN 50000
#define EE 1600000
#define GG 64
#define NODE_IN 32
#define HID 64
#define EDGE_IN 16
#define NLAYER 3

// ---------------- device scratch (static globals; no runtime alloc) ----------------
__device__ float d_h[NN * HID];
__device__ float d_qn[NN * HID];
__device__ float d_kn[NN * HID];
__device__ float d_vn[NN * HID];
__device__ float d_sn[NN * HID];
__device__ float d_qwn[NN * HID];   // per-node q.We projection (4 heads x 16 r, packed)
__device__ int   d_deg[NN];
__device__ int   d_offs[NN + 1];
__device__ int   d_cursor[NN];
__device__ int   d_bsum[64];
__device__ int2  d_sedge[EE];       // {src, eid} sorted by dst
__device__ float d_M[HID * HID];    // fused Wq x We matrix for qw GEMM
__device__ float d_bqw[HID];

__device__ __forceinline__ float ex2(float x) {
    float r;
    asm("ex2.approx.f32 %0, %1;" : "=f"(r) : "f"(x));
    return r;
}

// ---------------- preprocessing: counting sort of edges by dst ----------------
__global__ void zero_deg_kernel() {
    int i = blockIdx.x * blockDim.x + threadIdx.x;
    if (i < NN) d_deg[i] = 0;
}

__global__ void hist_kernel(const int* __restrict__ ei) {
    int e = blockIdx.x * blockDim.x + threadIdx.x;
    if (e < EE) atomicAdd(&d_deg[ei[EE + e]], 1);
}

__global__ void scan1_kernel() {
    __shared__ int s[1024];
    int t = threadIdx.x;
    int i = blockIdx.x * 1024 + t;
    int v = (i < NN) ? d_deg[i] : 0;
    s[t] = v;
    __syncthreads();
    for (int o = 1; o < 1024; o <<= 1) {
        int x = (t >= o) ? s[t - o] : 0;
        __syncthreads();
        s[t] += x;
        __syncthreads();
    }
    if (i < NN) d_offs[i] = s[t] - v;
    if (t == 1023) d_bsum[blockIdx.x] = s[t];
}

// scan3 folds the cross-block prefix: each block loads the <=64 block sums into
// smem and sums below its own block id.
__global__ void scan3_kernel(int nb) {
    __shared__ int pref[64];
    int t = threadIdx.x;
    if (t < nb) pref[t] = d_bsum[t];
    __syncthreads();
    int i = blockIdx.x * 256 + t;
    if (i < NN) {
        int b = i >> 10;
        int add = 0;
        for (int j = 0; j < b; j++) add += pref[j];
        int v = d_offs[i] + add;
        d_offs[i] = v;
        d_cursor[i] = v;
    }
    if (i == 0) {
        int tot = 0;
        for (int j = 0; j < nb; j++) tot += pref[j];
        d_offs[NN] = tot;   // == EE
    }
}

__global__ void scatter_kernel(const int* __restrict__ ei) {
    int e = blockIdx.x * blockDim.x + threadIdx.x;
    if (e < EE) {
        int dstv = ei[EE + e];
        int pos = atomicAdd(&d_cursor[dstv], 1);
        d_sedge[pos] = make_int2(ei[e], e);
    }
}

// ---------------- input embedding: h = relu(x @ Wn + bn) ----------------
__global__ __launch_bounds__(256) void node_in_kernel(const float* __restrict__ x,
                                                      const float* __restrict__ Wn,
                                                      const float* __restrict__ bn) {
    __shared__ float Wns[NODE_IN * HID];
    __shared__ float bns[HID];
    __shared__ float xs[4][NODE_IN];
    int t = threadIdx.x;
    for (int u = t; u < NODE_IN * HID; u += 256) Wns[u] = Wn[u];
    if (t < HID) bns[t] = bn[t];
    int j = t & 63, y = t >> 6;
    int node = blockIdx.x * 4 + y;
    if (j < NODE_IN && node < NN) xs[y][j] = x[node * NODE_IN + j];
    __syncthreads();
    if (node < NN) {
        float a = bns[j];
        #pragma unroll
        for (int k = 0; k < NODE_IN; k++) a += xs[y][k] * Wns[k * HID + j];
        d_h[(size_t)node * HID + j] = fmaxf(a, 0.f);
    }
}

// ---------------- per-layer M = per-head (Wq x We), bqw = per-head (bq x We) ------
__global__ void prep_M_kernel(const float* __restrict__ Wq, const float* __restrict__ bq,
                              const float* __restrict__ We, int layer) {
    int idx = blockIdx.x * 256 + threadIdx.x;
    const float* Wql = Wq + layer * HID * HID;
    const float* Wel = We + layer * EDGE_IN * HID;
    if (idx < HID * HID) {
        int krow = idx >> 6, col = idx & 63;
        int h = col >> 4, r = col & 15;
        float s = 0.f;
        #pragma unroll
        for (int c = 0; c < 16; c++)
            s += Wql[krow * HID + h * 16 + c] * Wel[r * HID + h * 16 + c];
        d_M[idx] = s;
    }
    if (idx < HID) {
        int h = idx >> 4, r = idx & 15;
        const float* bql = bq + layer * HID;
        float s = 0.f;
        #pragma unroll
        for (int c = 0; c < 16; c++)
            s += bql[h * 16 + c] * Wel[r * HID + h * 16 + c];
        d_bqw[idx] = s;
    }
}

// ---------------- fused Q/K/V/Skip/QW node GEMM (64 x 320 tile) -------------------
__global__ __launch_bounds__(256, 2) void qkvs_kernel(
    const float* __restrict__ Wq, const float* __restrict__ bq,
    const float* __restrict__ Wk, const float* __restrict__ bk,
    const float* __restrict__ Wv, const float* __restrict__ bv,
    const float* __restrict__ Ws, const float* __restrict__ bs, int layer) {
    extern __shared__ float sm[];
    float* hs = sm;            // 64 x 64
    float* ws = sm + 64 * 64;  // 64 x 320
    const float* Wm[5] = {Wq + layer * HID * HID, Wk + layer * HID * HID,
                          Wv + layer * HID * HID, Ws + layer * HID * HID, d_M};
    const float* bm[5] = {bq + layer * HID, bk + layer * HID, bv + layer * HID,
                          bs + layer * HID, d_bqw};
    float* outp[5] = {d_qn, d_kn, d_vn, d_sn, d_qwn};
    int t = threadIdx.x;
    int node0 = blockIdx.x * 64;

    #pragma unroll
    for (int u = 0; u < 20; u++) {
        int mat = u >> 2;
        int e0 = ((u & 3) * 256 + t) * 4;
        int k = e0 >> 6, jj = e0 & 63;
        float4 w4 = *reinterpret_cast<const float4*>(Wm[mat] + k * HID + jj);
        *reinterpret_cast<float4*>(ws + k * 320 + mat * 64 + jj) = w4;
    }
    #pragma unroll
    for (int u = 0; u < 4; u++) {
        int e0 = (u * 256 + t) * 4;
        int row = e0 >> 6, k = e0 & 63;
        int node = node0 + row;
        float4 h4 = make_float4(0.f, 0.f, 0.f, 0.f);
        if (node < NN) h4 = *reinterpret_cast<const float4*>(d_h + (size_t)node * HID + k);
        *reinterpret_cast<float4*>(hs + e0) = h4;
    }
    __syncthreads();

    int ry = t >> 5;
    int cx = t & 31;
    float acc[8][10];
    #pragma unroll
    for (int c = 0; c < 10; c++) {
        int mat = c >> 1;
        int jj = (c & 1) * 32 + cx;
        float b = bm[mat][jj];
        #pragma unroll
        for (int rr = 0; rr < 8; rr++) acc[rr][c] = b;
    }
    #pragma unroll 4
    for (int k0 = 0; k0 < 64; k0 += 4) {
        float4 hr4[8];
        #pragma unroll
        for (int rr = 0; rr < 8; rr++)
            hr4[rr] = *reinterpret_cast<const float4*>(hs + (ry * 8 + rr) * 64 + k0);
        #pragma unroll
        for (int kk = 0; kk < 4; kk++) {
            float wr[10];
            #pragma unroll
            for (int c = 0; c < 10; c++) wr[c] = ws[(k0 + kk) * 320 + cx + c * 32];
            #pragma unroll
            for (int rr = 0; rr < 8; rr++) {
                float hv = (kk == 0) ? hr4[rr].x : (kk == 1) ? hr4[rr].y
                         : (kk == 2) ? hr4[rr].z : hr4[rr].w;
                #pragma unroll
                for (int c = 0; c < 10; c++) acc[rr][c] += hv * wr[c];
            }
        }
    }
    #pragma unroll
    for (int rr = 0; rr < 8; rr++) {
        int node = node0 + ry * 8 + rr;
        if (node >= NN) continue;
        #pragma unroll
        for (int c = 0; c < 10; c++) {
            int mat = c >> 1;
            int jj = (c & 1) * 32 + cx;
            outp[mat][(size_t)node * HID + jj] = acc[rr][c];
        }
    }
}

// ---------------- fused attention: 8 lanes per edge, 4 streams per warp ----------
// lane = 8*s + 2*h + qh. Lane owns channels h*16+qh*8..+7 (2 float4s) and edge
// features 8*qh..+7. Score per head: local 8ch dot + 8-feat qw.e, one shfl_xor(1).
// Four parallel softmax streams merged with 2 xor rounds (8, 16). Warp-uniform
// trip count ceil(d/4); invalid slots clamp loads and contribute w=0.
// sedge prefetched depth-2, K/V/E depth-1.
__global__ __launch_bounds__(256) void attn_kernel(const float* __restrict__ We,
                                                   const float* __restrict__ ea,
                                                   int layer) {
    __shared__ float WeS[16 * 72];      // skewed: [r*72 + col + (col>>3)]
    int t = threadIdx.x;
    const float* Wel = We + layer * EDGE_IN * HID;
    for (int u = t; u < EDGE_IN * HID; u += 256) {
        int r = u >> 6, col = u & 63;
        WeS[r * 72 + col + (col >> 3)] = Wel[u];
    }
    __syncthreads();

    int lane = t & 31;
    int warp = t >> 5;
    int n = blockIdx.x * 8 + warp;
    if (n >= NN) return;

    int s  = lane >> 3;        // stream 0..3
    int l8 = lane & 7;
    int h  = l8 >> 1;          // head 0..3
    int qh = l8 & 1;           // channel/feature half
    int cb = h * 4 + qh * 2;   // float4 index within 16-float4 node row

    const float4* qn4  = reinterpret_cast<const float4*>(d_qn);
    const float4* qwn4 = reinterpret_cast<const float4*>(d_qwn);
    const float4* kn4  = reinterpret_cast<const float4*>(d_kn);
    const float4* vn4  = reinterpret_cast<const float4*>(d_vn);
    const float4* ea4  = reinterpret_cast<const float4*>(ea);

    float4 qa  = qn4[n * 16 + cb],  qb  = qn4[n * 16 + cb + 1];
    float4 qwa = qwn4[n * 16 + cb], qwb = qwn4[n * 16 + cb + 1];

    float m = -1e30f, den = 0.f;
    float4 a0 = make_float4(0.f, 0.f, 0.f, 0.f);
    float4 a1 = make_float4(0.f, 0.f, 0.f, 0.f);
    float4 g0 = make_float4(0.f, 0.f, 0.f, 0.f);   // eac chunk lo
    float4 g1 = make_float4(0.f, 0.f, 0.f, 0.f);   // eac chunk hi

    int beg = d_offs[n], end = d_offs[n + 1];
    int d = end - beg;
    int itmax = (d + 3) >> 2;          // warp-uniform trip count

    int i = beg + s;
    bool vld_cur = (i < end);
    bool vld_nxt = (i + 4 < end);
    int2 se_nxt = make_int2(0, 0);
    float4 ka, kb, va, vb, eca, ecb;
    if (itmax > 0) {
        int idx = vld_cur ? i : (end - 1);
        int2 se = d_sedge[idx];
        ka = kn4[se.x * 16 + cb];  kb = kn4[se.x * 16 + cb + 1];
        va = vn4[se.x * 16 + cb];  vb = vn4[se.x * 16 + cb + 1];
        eca = ea4[se.y * 4 + qh * 2]; ecb = ea4[se.y * 4 + qh * 2 + 1];
        if (itmax > 1) {
            int idx2 = vld_nxt ? (i + 4) : (end - 1);
            se_nxt = d_sedge[idx2];    // depth-2 prefetch of the index pair
        }
    }
    for (int it = 0; it < itmax; it++) {
        float4 cka = ka, ckb = kb, cva = va, cvb = vb, cea = eca, ceb = ecb;
        bool cvld = vld_cur;
        if (it + 1 < itmax) {
            ka = kn4[se_nxt.x * 16 + cb];  kb = kn4[se_nxt.x * 16 + cb + 1];
            va = vn4[se_nxt.x * 16 + cb];  vb = vn4[se_nxt.x * 16 + cb + 1];
            eca = ea4[se_nxt.y * 4 + qh * 2]; ecb = ea4[se_nxt.y * 4 + qh * 2 + 1];
            vld_cur = vld_nxt;
            int i8 = i + 8;
            bool v8 = (i8 < end);
            int idx8 = v8 ? i8 : (end - 1);
            se_nxt = d_sedge[idx8];
            vld_nxt = v8;
            i += 4;
        }
        float pp = qa.x * cka.x + qa.y * cka.y + qa.z * cka.z + qa.w * cka.w
                 + qb.x * ckb.x + qb.y * ckb.y + qb.z * ckb.z + qb.w * ckb.w
                 + qwa.x * cea.x + qwa.y * cea.y + qwa.z * cea.z + qwa.w * cea.w
                 + qwb.x * ceb.x + qwb.y * ceb.y + qwb.z * ceb.z + qwb.w * ceb.w;
        pp += __shfl_xor_sync(0xffffffffu, pp, 1);
        pp = cvld ? pp * 0.36067376022224085f : -1e30f;   // 0.25*log2(e)
        float w;
        if (cvld && pp > m) {          // new running max (rare)
            float sc = ex2(m - pp);
            m = pp;
            den *= sc;
            a0.x *= sc; a0.y *= sc; a0.z *= sc; a0.w *= sc;
            a1.x *= sc; a1.y *= sc; a1.z *= sc; a1.w *= sc;
            g0.x *= sc; g0.y *= sc; g0.z *= sc; g0.w *= sc;
            g1.x *= sc; g1.y *= sc; g1.z *= sc; g1.w *= sc;
            w = 1.0f;
        } else {
            w = ex2(pp - m);
            w = cvld ? w : 0.f;
        }
        den += w;
        a0.x += w * cva.x; a0.y += w * cva.y; a0.z += w * cva.z; a0.w += w * cva.w;
        a1.x += w * cvb.x; a1.y += w * cvb.y; a1.z += w * cvb.z; a1.w += w * cvb.w;
        g0.x += w * cea.x; g0.y += w * cea.y; g0.z += w * cea.z; g0.w += w * cea.w;
        g1.x += w * ceb.x; g1.y += w * ceb.y; g1.z += w * ceb.z; g1.w += w * ceb.w;
    }

    // merge the 4 streams: xor rounds at offset 8 then 16 (all lanes converged)
    #pragma unroll
    for (int off = 8; off <= 16; off <<= 1) {
        float om  = __shfl_xor_sync(0xffffffffu, m,   off);
        float odn = __shfl_xor_sync(0xffffffffu, den, off);
        float o0x = __shfl_xor_sync(0xffffffffu, a0.x, off);
        float o0y = __shfl_xor_sync(0xffffffffu, a0.y, off);
        float o0z = __shfl_xor_sync(0xffffffffu, a0.z, off);
        float o0w = __shfl_xor_sync(0xffffffffu, a0.w, off);
        float o1x = __shfl_xor_sync(0xffffffffu, a1.x, off);
        float o1y = __shfl_xor_sync(0xffffffffu, a1.y, off);
        float o1z = __shfl_xor_sync(0xffffffffu, a1.z, off);
        float o1w = __shfl_xor_sync(0xffffffffu, a1.w, off);
        float e0x = __shfl_xor_sync(0xffffffffu, g0.x, off);
        float e0y = __shfl_xor_sync(0xffffffffu, g0.y, off);
        float e0z = __shfl_xor_sync(0xffffffffu, g0.z, off);
        float e0w = __shfl_xor_sync(0xffffffffu, g0.w, off);
        float e1x = __shfl_xor_sync(0xffffffffu, g1.x, off);
        float e1y = __shfl_xor_sync(0xffffffffu, g1.y, off);
        float e1z = __shfl_xor_sync(0xffffffffu, g1.z, off);
        float e1w = __shfl_xor_sync(0xffffffffu, g1.w, off);
        float mm = fmaxf(m, om);
        float sA = ex2(m - mm), sB = ex2(om - mm);
        den = den * sA + odn * sB;
        a0.x = a0.x * sA + o0x * sB; a0.y = a0.y * sA + o0y * sB;
        a0.z = a0.z * sA + o0z * sB; a0.w = a0.w * sA + o0w * sB;
        a1.x = a1.x * sA + o1x * sB; a1.y = a1.y * sA + o1y * sB;
        a1.z = a1.z * sA + o1z * sB; a1.w = a1.w * sA + o1w * sB;
        g0.x = g0.x * sA + e0x * sB; g0.y = g0.y * sA + e0y * sB;
        g0.z = g0.z * sA + e0z * sB; g0.w = g0.w * sA + e0w * sB;
        g1.x = g1.x * sA + e1x * sB; g1.y = g1.y * sA + e1y * sB;
        g1.z = g1.z * sA + e1z * sB; g1.w = g1.w * sA + e1w * sB;
        m = mm;
    }

    // fold edge-embedding: acc[c] += sum_r eac[h][r] * We[r][c]
    // eac[h][r] lives on lane (any s, h, qh=r>>3), reg (r&7).
    float ear[8] = {g0.x, g0.y, g0.z, g0.w, g1.x, g1.y, g1.z, g1.w};
    int colb = h * 16 + qh * 8;
    int sk = colb + (colb >> 3);       // skewed column base (consecutive 8 valid)
    #pragma unroll
    for (int r = 0; r < 16; r++) {
        int srcLane = (lane & 24) | (h << 1) | (r >> 3);
        float ev = __shfl_sync(0xffffffffu, ear[r & 7], srcLane);
        const float* wr = WeS + r * 72 + sk;
        a0.x += ev * wr[0]; a0.y += ev * wr[1]; a0.z += ev * wr[2]; a0.w += ev * wr[3];
        a1.x += ev * wr[4]; a1.y += ev * wr[5]; a1.z += ev * wr[6]; a1.w += ev * wr[7];
    }

    if (s == 0) {
        float inv = 1.f / (den + 1e-16f);
        const float4* sn4 = reinterpret_cast<const float4*>(d_sn);
        float4* h4p = reinterpret_cast<float4*>(d_h);
        float4 s4a = sn4[n * 16 + cb], s4b = sn4[n * 16 + cb + 1];
        float4 ha = h4p[n * 16 + cb], hb = h4p[n * 16 + cb + 1];
        ha.x += fmaxf(a0.x * inv + s4a.x, 0.f);
        ha.y += fmaxf(a0.y * inv + s4a.y, 0.f);
        ha.z += fmaxf(a0.z * inv + s4a.z, 0.f);
        ha.w += fmaxf(a0.w * inv + s4a.w, 0.f);
        hb.x += fmaxf(a1.x * inv + s4b.x, 0.f);
        hb.y += fmaxf(a1.y * inv + s4b.y, 0.f);
        hb.z += fmaxf(a1.z * inv + s4b.z, 0.f);
        hb.w += fmaxf(a1.w * inv + s4b.w, 0.f);
        h4p[n * 16 + cb] = ha;
        h4p[n * 16 + cb + 1] = hb;
    }
}

// ---------------- fused mean pool (sorted batch) + readout MLP -------------------
__global__ __launch_bounds__(1024) void pool_mlp_kernel(const int* __restrict__ batch,
    const float* __restrict__ W1, const float* __restrict__ b1,
    const float* __restrict__ W2, const float* __restrict__ b2,
    float* __restrict__ out) {
    __shared__ float red[1024];
    __shared__ float sp[64];
    __shared__ int bnd[2];
    int g = blockIdx.x, t = threadIdx.x;
    if (t == 0) {
        int lo = 0, hi = NN;
        while (lo < hi) { int mid = (lo + hi) >> 1; if (batch[mid] < g) lo = mid + 1; else hi = mid; }
        bnd[0] = lo;
        int lo2 = lo, hi2 = NN;
        while (lo2 < hi2) { int mid = (lo2 + hi2) >> 1; if (batch[mid] < g + 1) lo2 = mid + 1; else hi2 = mid; }
        bnd[1] = lo2;
    }
    __syncthreads();
    int lo = bnd[0], hi = bnd[1];
    int ch = t & 63, rg = t >> 6;     // 16 row groups
    float a = 0.f;
    for (int nd = lo + rg; nd < hi; nd += 16) a += d_h[(size_t)nd * HID + ch];
    red[t] = a;
    __syncthreads();
    if (t < 64) {
        float s = 0.f;
        #pragma unroll
        for (int j = 0; j < 16; j++) s += red[t + 64 * j];
        sp[t] = s / fmaxf((float)(hi - lo), 1.0f);
    }
    __syncthreads();
    if (t < 32) {
        float accv = b1[t];
        #pragma unroll
        for (int k = 0; k < HID; k++) accv += sp[k] * W1[k * 32 + t];
        float v = fmaxf(accv, 0.f) * W2[t];
        #pragma unroll
        for (int o = 16; o; o >>= 1) v += __shfl_xor_sync(0xffffffffu, v, o);
        if (t == 0) out[g] = v + b2[0];
    }
}

// ---------------- launch ----------------
extern "C" void kernel_launch(void* const* d_in, const int* in_sizes, int n_in,
                              void* d_out, int out_size) {
    const float* x   = (const float*)d_in[0];
    const int*   ei  = (const int*)d_in[1];
    const float* ea  = (const float*)d_in[2];
    const int*   bat = (const int*)d_in[3];
    const float* Wn  = (const float*)d_in[4];
    const float* bn  = (const float*)d_in[5];
    const float* Wq  = (const float*)d_in[6];
    const float* bq  = (const float*)d_in[7];
    const float* Wk  = (const float*)d_in[8];
    const float* bk  = (const float*)d_in[9];
    const float* Wv  = (const float*)d_in[10];
    const float* bv  = (const float*)d_in[11];
    const float* We  = (const float*)d_in[12];
    const float* Ws  = (const float*)d_in[13];
    const float* bs  = (const float*)d_in[14];
    const float* W1  = (const float*)d_in[15];
    const float* b1  = (const float*)d_in[16];
    const float* W2  = (const float*)d_in[17];
    const float* b2  = (const float*)d_in[18];
    float* out = (float*)d_out;

    cudaFuncSetAttribute(qkvs_kernel, cudaFuncAttributeMaxDynamicSharedMemorySize, 100 * 1024);

    // 1) counting sort of edges by dst -> CSR of {src, eid}
    zero_deg_kernel<<<(NN + 255) / 256, 256>>>();
    hist_kernel<<<(EE + 255) / 256, 256>>>(ei);
    int nb = (NN + 1023) / 1024;
    scan1_kernel<<<nb, 1024>>>();
    scan3_kernel<<<(NN + 255) / 256, 256>>>(nb);
    scatter_kernel<<<(EE + 255) / 256, 256>>>(ei);

    // 2) input embedding
    node_in_kernel<<<(NN + 3) / 4, 256>>>(x, Wn, bn);

    // 3) transformer conv layers
    for (int l = 0; l < NLAYER; l++) {
        prep_M_kernel<<<16, 256>>>(Wq, bq, We, l);
        qkvs_kernel<<<(NN + 63) / 64, 256, (64 * 64 + 64 * 320) * 4>>>(
            Wq, bq, Wk, bk, Wv, bv, Ws, bs, l);
        attn_kernel<<<(NN + 7) / 8, 256>>>(We, ea, l);
    }

    // 4) fused mean pool + MLP head (batch is sorted)
    pool_mlp_kernel<<<GG, 1024>>>(bat, W1, b1, W2, b2, out);
}

// round 8
// speedup vs baseline: 1.2044x; 1.2044x over previous
#include <cuda_runtime.h>
#include <cuda_fp16.h>
#include <math.h>

#define NN 50000
#define EE 1600000
#define GG 64
#define NODE_IN 32
#define HID 64
#define EDGE_IN 16
#define NLAYER 3

// ---------------- device scratch (static globals; no runtime alloc) ----------------
__device__ float d_h[NN * HID];
__device__ float d_qn[NN * HID];
__device__ __align__(16) __half d_knh[NN * HID];   // K in fp16 (halved gather bytes)
__device__ __align__(16) __half d_vnh[NN * HID];   // V in fp16
__device__ float d_sn[NN * HID];
__device__ float d_qwn[NN * HID];   // per-node q.We projection (4 heads x 16 r, packed)
__device__ int   d_deg[NN];
__device__ int   d_offs[NN + 1];
__device__ int   d_cursor[NN];
__device__ int   d_bsum[64];
__device__ int2  d_sedge[EE];       // {src, eid} sorted by dst
__device__ float d_M[HID * HID];    // fused Wq x We matrix for qw GEMM
__device__ float d_bqw[HID];

__device__ __forceinline__ float ex2(float x) {
    float r;
    asm("ex2.approx.f32 %0, %1;" : "=f"(r) : "f"(x));
    return r;
}

// ---------------- preprocessing: counting sort of edges by dst ----------------
__global__ void zero_deg_kernel() {
    int i = blockIdx.x * blockDim.x + threadIdx.x;
    if (i < NN) d_deg[i] = 0;
}

__global__ void hist_kernel(const int* __restrict__ ei) {
    int e = blockIdx.x * blockDim.x + threadIdx.x;
    if (e < EE) atomicAdd(&d_deg[ei[EE + e]], 1);
}

__global__ void scan1_kernel() {
    __shared__ int s[1024];
    int t = threadIdx.x;
    int i = blockIdx.x * 1024 + t;
    int v = (i < NN) ? d_deg[i] : 0;
    s[t] = v;
    __syncthreads();
    for (int o = 1; o < 1024; o <<= 1) {
        int x = (t >= o) ? s[t - o] : 0;
        __syncthreads();
        s[t] += x;
        __syncthreads();
    }
    if (i < NN) d_offs[i] = s[t] - v;
    if (t == 1023) d_bsum[blockIdx.x] = s[t];
}

// scan3 folds the cross-block prefix: each block loads the <=64 block sums into
// smem and sums below its own block id.
__global__ void scan3_kernel(int nb) {
    __shared__ int pref[64];
    int t = threadIdx.x;
    if (t < nb) pref[t] = d_bsum[t];
    __syncthreads();
    int i = blockIdx.x * 256 + t;
    if (i < NN) {
        int b = i >> 10;
        int add = 0;
        for (int j = 0; j < b; j++) add += pref[j];
        int v = d_offs[i] + add;
        d_offs[i] = v;
        d_cursor[i] = v;
    }
    if (i == 0) {
        int tot = 0;
        for (int j = 0; j < nb; j++) tot += pref[j];
        d_offs[NN] = tot;   // == EE
    }
}

__global__ void scatter_kernel(const int* __restrict__ ei) {
    int e = blockIdx.x * blockDim.x + threadIdx.x;
    if (e < EE) {
        int dstv = ei[EE + e];
        int pos = atomicAdd(&d_cursor[dstv], 1);
        d_sedge[pos] = make_int2(ei[e], e);
    }
}

// ---------------- input embedding: h = relu(x @ Wn + bn) ----------------
__global__ __launch_bounds__(256) void node_in_kernel(const float* __restrict__ x,
                                                      const float* __restrict__ Wn,
                                                      const float* __restrict__ bn) {
    __shared__ float Wns[NODE_IN * HID];
    __shared__ float bns[HID];
    __shared__ float xs[4][NODE_IN];
    int t = threadIdx.x;
    for (int u = t; u < NODE_IN * HID; u += 256) Wns[u] = Wn[u];
    if (t < HID) bns[t] = bn[t];
    int j = t & 63, y = t >> 6;
    int node = blockIdx.x * 4 + y;
    if (j < NODE_IN && node < NN) xs[y][j] = x[node * NODE_IN + j];
    __syncthreads();
    if (node < NN) {
        float a = bns[j];
        #pragma unroll
        for (int k = 0; k < NODE_IN; k++) a += xs[y][k] * Wns[k * HID + j];
        d_h[(size_t)node * HID + j] = fmaxf(a, 0.f);
    }
}

// ---------------- per-layer M = per-head (Wq x We), bqw = per-head (bq x We) ------
__global__ void prep_M_kernel(const float* __restrict__ Wq, const float* __restrict__ bq,
                              const float* __restrict__ We, int layer) {
    int idx = blockIdx.x * 256 + threadIdx.x;
    const float* Wql = Wq + layer * HID * HID;
    const float* Wel = We + layer * EDGE_IN * HID;
    if (idx < HID * HID) {
        int krow = idx >> 6, col = idx & 63;
        int h = col >> 4, r = col & 15;
        float s = 0.f;
        #pragma unroll
        for (int c = 0; c < 16; c++)
            s += Wql[krow * HID + h * 16 + c] * Wel[r * HID + h * 16 + c];
        d_M[idx] = s;
    }
    if (idx < HID) {
        int h = idx >> 4, r = idx & 15;
        const float* bql = bq + layer * HID;
        float s = 0.f;
        #pragma unroll
        for (int c = 0; c < 16; c++)
            s += bql[h * 16 + c] * Wel[r * HID + h * 16 + c];
        d_bqw[idx] = s;
    }
}

// ---------------- fused Q/K/V/Skip/QW node GEMM (64 x 320 tile) -------------------
// K (mat 1) and V (mat 2) are written as fp16; Q/S/QW stay fp32.
__global__ __launch_bounds__(256, 2) void qkvs_kernel(
    const float* __restrict__ Wq, const float* __restrict__ bq,
    const float* __restrict__ Wk, const float* __restrict__ bk,
    const float* __restrict__ Wv, const float* __restrict__ bv,
    const float* __restrict__ Ws, const float* __restrict__ bs, int layer) {
    extern __shared__ float sm[];
    float* hs = sm;            // 64 x 64
    float* ws = sm + 64 * 64;  // 64 x 320
    const float* Wm[5] = {Wq + layer * HID * HID, Wk + layer * HID * HID,
                          Wv + layer * HID * HID, Ws + layer * HID * HID, d_M};
    const float* bm[5] = {bq + layer * HID, bk + layer * HID, bv + layer * HID,
                          bs + layer * HID, d_bqw};
    int t = threadIdx.x;
    int node0 = blockIdx.x * 64;

    #pragma unroll
    for (int u = 0; u < 20; u++) {
        int mat = u >> 2;
        int e0 = ((u & 3) * 256 + t) * 4;
        int k = e0 >> 6, jj = e0 & 63;
        float4 w4 = *reinterpret_cast<const float4*>(Wm[mat] + k * HID + jj);
        *reinterpret_cast<float4*>(ws + k * 320 + mat * 64 + jj) = w4;
    }
    #pragma unroll
    for (int u = 0; u < 4; u++) {
        int e0 = (u * 256 + t) * 4;
        int row = e0 >> 6, k = e0 & 63;
        int node = node0 + row;
        float4 h4 = make_float4(0.f, 0.f, 0.f, 0.f);
        if (node < NN) h4 = *reinterpret_cast<const float4*>(d_h + (size_t)node * HID + k);
        *reinterpret_cast<float4*>(hs + e0) = h4;
    }
    __syncthreads();

    int ry = t >> 5;
    int cx = t & 31;
    float acc[8][10];
    #pragma unroll
    for (int c = 0; c < 10; c++) {
        int mat = c >> 1;
        int jj = (c & 1) * 32 + cx;
        float b = bm[mat][jj];
        #pragma unroll
        for (int rr = 0; rr < 8; rr++) acc[rr][c] = b;
    }
    #pragma unroll 4
    for (int k0 = 0; k0 < 64; k0 += 4) {
        float4 hr4[8];
        #pragma unroll
        for (int rr = 0; rr < 8; rr++)
            hr4[rr] = *reinterpret_cast<const float4*>(hs + (ry * 8 + rr) * 64 + k0);
        #pragma unroll
        for (int kk = 0; kk < 4; kk++) {
            float wr[10];
            #pragma unroll
            for (int c = 0; c < 10; c++) wr[c] = ws[(k0 + kk) * 320 + cx + c * 32];
            #pragma unroll
            for (int rr = 0; rr < 8; rr++) {
                float hv = (kk == 0) ? hr4[rr].x : (kk == 1) ? hr4[rr].y
                         : (kk == 2) ? hr4[rr].z : hr4[rr].w;
                #pragma unroll
                for (int c = 0; c < 10; c++) acc[rr][c] += hv * wr[c];
            }
        }
    }
    #pragma unroll
    for (int rr = 0; rr < 8; rr++) {
        int node = node0 + ry * 8 + rr;
        if (node >= NN) continue;
        #pragma unroll
        for (int c = 0; c < 10; c++) {
            int mat = c >> 1;
            int jj = (c & 1) * 32 + cx;
            size_t off = (size_t)node * HID + jj;
            if (mat == 0)      d_qn[off] = acc[rr][c];
            else if (mat == 1) d_knh[off] = __float2half_rn(acc[rr][c]);
            else if (mat == 2) d_vnh[off] = __float2half_rn(acc[rr][c]);
            else if (mat == 3) d_sn[off] = acc[rr][c];
            else               d_qwn[off] = acc[rr][c];
        }
    }
}

// ---------------- fused attention: half-warp per edge, warp per node -------------
// lane = 16*hf + 4*head + p ; lane owns channels (4h+p)*4..+3, edge-feats p*4..+3.
// K/V gathered as fp16 (uint2 = 4 halves per lane -> one 128B line per node row).
// Two parallel softmax streams (one per half), merged at the end. Warp-uniform
// trip count; trailing invalid slot clamps loads and contributes w=0.
// d_sedge prefetched DEPTH 2; K/V/E depth 1.
__global__ __launch_bounds__(256) void attn_kernel(const float* __restrict__ We,
                                                   const float* __restrict__ ea,
                                                   int layer) {
    __shared__ float WeS[16 * 68 + 4];  // skewed: [r*68 + col + (col>>4)]
    int t = threadIdx.x;
    const float* Wel = We + layer * EDGE_IN * HID;
    for (int u = t; u < EDGE_IN * HID; u += 256) {
        int r = u >> 6, col = u & 63;
        WeS[r * 68 + col + (col >> 4)] = Wel[u];
    }
    __syncthreads();

    int lane = t & 31;
    int warp = t >> 5;
    int n = blockIdx.x * 8 + warp;
    if (n >= NN) return;

    int hf = lane >> 4;
    int hl = lane & 15;
    int h = hl >> 2;
    int p = hl & 3;
    int cbs = hl * 4 + h;

    float4 q  = reinterpret_cast<const float4*>(d_qn)[n * 16 + hl];
    float4 qw = reinterpret_cast<const float4*>(d_qwn)[n * 16 + hl];

    float m = -1e30f, den = 0.f;
    float4 acc = make_float4(0.f, 0.f, 0.f, 0.f);
    float4 eac = make_float4(0.f, 0.f, 0.f, 0.f);

    int beg = d_offs[n], end = d_offs[n + 1];
    int d = end - beg;
    int itmax = (d + 1) >> 1;          // warp-uniform trip count

    int i = beg + hf;                  // current edge index for this stream
    bool vld_cur = (i < end);
    bool vld_nxt = (i + 2 < end);
    int2 se_nxt = make_int2(0, 0);
    uint2 kr, vr;                      // 4 halves each
    float4 e4;
    if (itmax > 0) {
        int idx = vld_cur ? i : (end - 1);
        int2 se = d_sedge[idx];
        kr = *reinterpret_cast<const uint2*>(d_knh + (size_t)se.x * HID + hl * 4);
        vr = *reinterpret_cast<const uint2*>(d_vnh + (size_t)se.x * HID + hl * 4);
        e4 = reinterpret_cast<const float4*>(ea)[se.y * 4 + p];
        if (itmax > 1) {
            int idx2 = vld_nxt ? (i + 2) : (end - 1);
            se_nxt = d_sedge[idx2];    // depth-2 prefetch of the index pair
        }
    }
    for (int it = 0; it < itmax; it++) {
        uint2 ckr = kr, cvr = vr;
        float4 ce = e4;
        bool cvld = vld_cur;
        if (it + 1 < itmax) {
            // gathers for it+1 use the ALREADY-RESIDENT se_nxt (no serial chain)
            kr = *reinterpret_cast<const uint2*>(d_knh + (size_t)se_nxt.x * HID + hl * 4);
            vr = *reinterpret_cast<const uint2*>(d_vnh + (size_t)se_nxt.x * HID + hl * 4);
            e4 = reinterpret_cast<const float4*>(ea)[se_nxt.y * 4 + p];
            vld_cur = vld_nxt;
            int i4 = i + 4;            // prefetch index pair for it+2
            bool v4b = (i4 < end);
            int idx4 = v4b ? i4 : (end - 1);
            se_nxt = d_sedge[idx4];
            vld_nxt = v4b;
            i += 2;
        }
        float2 k01 = __half22float2(*reinterpret_cast<const __half2*>(&ckr.x));
        float2 k23 = __half22float2(*reinterpret_cast<const __half2*>(&ckr.y));
        float2 v01 = __half22float2(*reinterpret_cast<const __half2*>(&cvr.x));
        float2 v23 = __half22float2(*reinterpret_cast<const __half2*>(&cvr.y));
        float pp = q.x * k01.x + q.y * k01.y + q.z * k23.x + q.w * k23.y
                 + qw.x * ce.x + qw.y * ce.y + qw.z * ce.z + qw.w * ce.w;
        pp += __shfl_xor_sync(0xffffffffu, pp, 1);
        pp += __shfl_xor_sync(0xffffffffu, pp, 2);
        pp = cvld ? pp * 0.36067376022224085f : -1e30f;   // 0.25*log2(e); -inf if invalid
        float w;
        if (cvld && pp > m) {          // new running max (rare)
            float sc = ex2(m - pp);
            m = pp;
            den *= sc;
            acc.x *= sc; acc.y *= sc; acc.z *= sc; acc.w *= sc;
            eac.x *= sc; eac.y *= sc; eac.z *= sc; eac.w *= sc;
            w = 1.0f;
        } else {
            w = ex2(pp - m);           // invalid: pp-m=0 -> w=1, zeroed below
            w = cvld ? w : 0.f;
        }
        den += w;
        acc.x += w * v01.x; acc.y += w * v01.y; acc.z += w * v23.x; acc.w += w * v23.y;
        eac.x += w * ce.x;  eac.y += w * ce.y;  eac.z += w * ce.z;  eac.w += w * ce.w;
    }

    // fold edge-embedding: acc[c] += sum_r eacc[h][r] * We[r][c]   (conflict-free smem)
    float ea_arr[4] = {eac.x, eac.y, eac.z, eac.w};
    #pragma unroll
    for (int r = 0; r < 16; r++) {
        float ev = __shfl_sync(0xffffffffu, ea_arr[r & 3], (h << 2) + (r >> 2), 16);
        acc.x += ev * WeS[r * 68 + cbs + 0];
        acc.y += ev * WeS[r * 68 + cbs + 1];
        acc.z += ev * WeS[r * 68 + cbs + 2];
        acc.w += ev * WeS[r * 68 + cbs + 3];
    }

    // merge the two half-warp softmax streams
    float om  = __shfl_xor_sync(0xffffffffu, m,    16);
    float odn = __shfl_xor_sync(0xffffffffu, den,  16);
    float oax = __shfl_xor_sync(0xffffffffu, acc.x, 16);
    float oay = __shfl_xor_sync(0xffffffffu, acc.y, 16);
    float oaz = __shfl_xor_sync(0xffffffffu, acc.z, 16);
    float oaw = __shfl_xor_sync(0xffffffffu, acc.w, 16);
    float mm = fmaxf(m, om);
    float sA = ex2(m - mm), sB = ex2(om - mm);
    den = den * sA + odn * sB;
    float ox = acc.x * sA + oax * sB;
    float oy = acc.y * sA + oay * sB;
    float oz = acc.z * sA + oaz * sB;
    float ow = acc.w * sA + oaw * sB;

    if (hf == 0) {
        float inv = 1.f / (den + 1e-16f);
        float4 s4 = reinterpret_cast<const float4*>(d_sn)[n * 16 + hl];
        float4 hc = reinterpret_cast<const float4*>(d_h)[n * 16 + hl];
        hc.x += fmaxf(ox * inv + s4.x, 0.f);
        hc.y += fmaxf(oy * inv + s4.y, 0.f);
        hc.z += fmaxf(oz * inv + s4.z, 0.f);
        hc.w += fmaxf(ow * inv + s4.w, 0.f);
        reinterpret_cast<float4*>(d_h)[n * 16 + hl] = hc;
    }
}

// ---------------- fused mean pool (sorted batch) + readout MLP -------------------
__global__ __launch_bounds__(1024) void pool_mlp_kernel(const int* __restrict__ batch,
    const float* __restrict__ W1, const float* __restrict__ b1,
    const float* __restrict__ W2, const float* __restrict__ b2,
    float* __restrict__ out) {
    __shared__ float red[1024];
    __shared__ float sp[64];
    __shared__ int bnd[2];
    int g = blockIdx.x, t = threadIdx.x;
    if (t == 0) {
        int lo = 0, hi = NN;
        while (lo < hi) { int mid = (lo + hi) >> 1; if (batch[mid] < g) lo = mid + 1; else hi = mid; }
        bnd[0] = lo;
        int lo2 = lo, hi2 = NN;
        while (lo2 < hi2) { int mid = (lo2 + hi2) >> 1; if (batch[mid] < g + 1) lo2 = mid + 1; else hi2 = mid; }
        bnd[1] = lo2;
    }
    __syncthreads();
    int lo = bnd[0], hi = bnd[1];
    int ch = t & 63, rg = t >> 6;     // 16 row groups
    float a = 0.f;
    for (int nd = lo + rg; nd < hi; nd += 16) a += d_h[(size_t)nd * HID + ch];
    red[t] = a;
    __syncthreads();
    if (t < 64) {
        float s = 0.f;
        #pragma unroll
        for (int j = 0; j < 16; j++) s += red[t + 64 * j];
        sp[t] = s / fmaxf((float)(hi - lo), 1.0f);
    }
    __syncthreads();
    if (t < 32) {
        float accv = b1[t];
        #pragma unroll
        for (int k = 0; k < HID; k++) accv += sp[k] * W1[k * 32 + t];
        float v = fmaxf(accv, 0.f) * W2[t];
        #pragma unroll
        for (int o = 16; o; o >>= 1) v += __shfl_xor_sync(0xffffffffu, v, o);
        if (t == 0) out[g] = v + b2[0];
    }
}

// ---------------- launch ----------------
extern "C" void kernel_launch(void* const* d_in, const int* in_sizes, int n_in,
                              void* d_out, int out_size) {
    const float* x   = (const float*)d_in[0];
    const int*   ei  = (const int*)d_in[1];
    const float* ea  = (const float*)d_in[2];
    const int*   bat = (const int*)d_in[3];
    const float* Wn  = (const float*)d_in[4];
    const float* bn  = (const float*)d_in[5];
    const float* Wq  = (const float*)d_in[6];
    const float* bq  = (const float*)d_in[7];
    const float* Wk  = (const float*)d_in[8];
    const float* bk  = (const float*)d_in[9];
    const float* Wv  = (const float*)d_in[10];
    const float* bv  = (const float*)d_in[11];
    const float* We  = (const float*)d_in[12];
    const float* Ws  = (const float*)d_in[13];
    const float* bs  = (const float*)d_in[14];
    const float* W1  = (const float*)d_in[15];
    const float* b1  = (const float*)d_in[16];
    const float* W2  = (const float*)d_in[17];
    const float* b2  = (const float*)d_in[18];
    float* out = (float*)d_out;

    cudaFuncSetAttribute(qkvs_kernel, cudaFuncAttributeMaxDynamicSharedMemorySize, 100 * 1024);

    // 1) counting sort of edges by dst -> CSR of {src, eid}
    zero_deg_kernel<<<(NN + 255) / 256, 256>>>();
    hist_kernel<<<(EE + 255) / 256, 256>>>(ei);
    int nb = (NN + 1023) / 1024;
    scan1_kernel<<<nb, 1024>>>();
    scan3_kernel<<<(NN + 255) / 256, 256>>>(nb);
    scatter_kernel<<<(EE + 255) / 256, 256>>>(ei);

    // 2) input embedding
    node_in_kernel<<<(NN + 3) / 4, 256>>>(x, Wn, bn);

    // 3) transformer conv layers
    for (int l = 0; l < NLAYER; l++) {
        prep_M_kernel<<<16, 256>>>(Wq, bq, We, l);
        qkvs_kernel<<<(NN + 63) / 64, 256, (64 * 64 + 64 * 320) * 4>>>(
            Wq, bq, Wk, bk, Wv, bv, Ws, bs, l);
        attn_kernel<<<(NN + 7) / 8, 256>>>(We, ea, l);
    }

    // 4) fused mean pool + MLP head (batch is sorted)
    pool_mlp_kernel<<<GG, 1024>>>(bat, W1, b1, W2, b2, out);
}

// round 9
// speedup vs baseline: 1.2496x; 1.0376x over previous
#include <cuda_runtime.h>
#include <cuda_fp16.h>
#include <math.h>

#define NN 50000
#define EE 1600000
#define GG 64
#define NODE_IN 32
#define HID 64
#define EDGE_IN 16
#define NLAYER 3

// ---------------- device scratch (static globals; no runtime alloc) ----------------
__device__ float d_h[NN * HID];
__device__ float d_qn[NN * HID];
__device__ __align__(16) __half d_knh[NN * HID];   // K in fp16 (halved gather bytes)
__device__ __align__(16) __half d_vnh[NN * HID];   // V in fp16
__device__ float d_sn[NN * HID];
__device__ float d_qwn[NN * HID];   // per-node q.We projection (4 heads x 16 r, packed)
__device__ int   d_deg[NN];
__device__ int   d_offs[NN + 1];
__device__ int   d_cursor[NN];
__device__ int   d_bsum[64];
__device__ int2  d_sedge[EE];       // {src, eid} sorted by dst
__device__ float d_M[NLAYER * HID * HID];   // fused Wq x We matrices (all layers)
__device__ float d_bqw[NLAYER * HID];

__device__ __forceinline__ float ex2(float x) {
    float r;
    asm("ex2.approx.f32 %0, %1;" : "=f"(r) : "f"(x));
    return r;
}

// ---------------- preprocessing: counting sort of edges by dst ----------------
__global__ void zero_deg_kernel() {
    int i = blockIdx.x * blockDim.x + threadIdx.x;
    if (i < NN) d_deg[i] = 0;
}

__global__ void hist_kernel(const int* __restrict__ ei) {
    int e = blockIdx.x * blockDim.x + threadIdx.x;
    if (e < EE) atomicAdd(&d_deg[ei[EE + e]], 1);
}

__global__ void scan1_kernel() {
    __shared__ int s[1024];
    int t = threadIdx.x;
    int i = blockIdx.x * 1024 + t;
    int v = (i < NN) ? d_deg[i] : 0;
    s[t] = v;
    __syncthreads();
    for (int o = 1; o < 1024; o <<= 1) {
        int x = (t >= o) ? s[t - o] : 0;
        __syncthreads();
        s[t] += x;
        __syncthreads();
    }
    if (i < NN) d_offs[i] = s[t] - v;
    if (t == 1023) d_bsum[blockIdx.x] = s[t];
}

// scan3 folds the cross-block prefix: each block loads the <=64 block sums into
// smem and sums below its own block id.
__global__ void scan3_kernel(int nb) {
    __shared__ int pref[64];
    int t = threadIdx.x;
    if (t < nb) pref[t] = d_bsum[t];
    __syncthreads();
    int i = blockIdx.x * 256 + t;
    if (i < NN) {
        int b = i >> 10;
        int add = 0;
        for (int j = 0; j < b; j++) add += pref[j];
        int v = d_offs[i] + add;
        d_offs[i] = v;
        d_cursor[i] = v;
    }
    if (i == 0) {
        int tot = 0;
        for (int j = 0; j < nb; j++) tot += pref[j];
        d_offs[NN] = tot;   // == EE
    }
}

__global__ void scatter_kernel(const int* __restrict__ ei) {
    int e = blockIdx.x * blockDim.x + threadIdx.x;
    if (e < EE) {
        int dstv = ei[EE + e];
        int pos = atomicAdd(&d_cursor[dstv], 1);
        d_sedge[pos] = make_int2(ei[e], e);
    }
}

// ---------------- input embedding: h = relu(x @ Wn + bn) ----------------
__global__ __launch_bounds__(256) void node_in_kernel(const float* __restrict__ x,
                                                      const float* __restrict__ Wn,
                                                      const float* __restrict__ bn) {
    __shared__ float Wns[NODE_IN * HID];
    __shared__ float bns[HID];
    __shared__ float xs[4][NODE_IN];
    int t = threadIdx.x;
    for (int u = t; u < NODE_IN * HID; u += 256) Wns[u] = Wn[u];
    if (t < HID) bns[t] = bn[t];
    int j = t & 63, y = t >> 6;
    int node = blockIdx.x * 4 + y;
    if (j < NODE_IN && node < NN) xs[y][j] = x[node * NODE_IN + j];
    __syncthreads();
    if (node < NN) {
        float a = bns[j];
        #pragma unroll
        for (int k = 0; k < NODE_IN; k++) a += xs[y][k] * Wns[k * HID + j];
        d_h[(size_t)node * HID + j] = fmaxf(a, 0.f);
    }
}

// ---------------- all layers: M = per-head (Wq x We), bqw = per-head (bq x We) ----
__global__ void prep_M_kernel(const float* __restrict__ Wq, const float* __restrict__ bq,
                              const float* __restrict__ We) {
    int layer = blockIdx.y;
    int idx = blockIdx.x * 256 + threadIdx.x;
    const float* Wql = Wq + layer * HID * HID;
    const float* Wel = We + layer * EDGE_IN * HID;
    if (idx < HID * HID) {
        int krow = idx >> 6, col = idx & 63;
        int h = col >> 4, r = col & 15;
        float s = 0.f;
        #pragma unroll
        for (int c = 0; c < 16; c++)
            s += Wql[krow * HID + h * 16 + c] * Wel[r * HID + h * 16 + c];
        d_M[layer * HID * HID + idx] = s;
    }
    if (idx < HID) {
        int h = idx >> 4, r = idx & 15;
        const float* bql = bq + layer * HID;
        float s = 0.f;
        #pragma unroll
        for (int c = 0; c < 16; c++)
            s += bql[h * 16 + c] * Wel[r * HID + h * 16 + c];
        d_bqw[layer * HID + idx] = s;
    }
}

// ---------------- fused Q/K/V/Skip/QW node GEMM (64 x 320 tile) -------------------
// K (mat 1) and V (mat 2) are written as fp16; Q/S/QW stay fp32.
__global__ __launch_bounds__(256, 2) void qkvs_kernel(
    const float* __restrict__ Wq, const float* __restrict__ bq,
    const float* __restrict__ Wk, const float* __restrict__ bk,
    const float* __restrict__ Wv, const float* __restrict__ bv,
    const float* __restrict__ Ws, const float* __restrict__ bs, int layer) {
    extern __shared__ float sm[];
    float* hs = sm;            // 64 x 64
    float* ws = sm + 64 * 64;  // 64 x 320
    const float* Wm[5] = {Wq + layer * HID * HID, Wk + layer * HID * HID,
                          Wv + layer * HID * HID, Ws + layer * HID * HID,
                          d_M + layer * HID * HID};
    const float* bm[5] = {bq + layer * HID, bk + layer * HID, bv + layer * HID,
                          bs + layer * HID, d_bqw + layer * HID};
    int t = threadIdx.x;
    int node0 = blockIdx.x * 64;

    #pragma unroll
    for (int u = 0; u < 20; u++) {
        int mat = u >> 2;
        int e0 = ((u & 3) * 256 + t) * 4;
        int k = e0 >> 6, jj = e0 & 63;
        float4 w4 = *reinterpret_cast<const float4*>(Wm[mat] + k * HID + jj);
        *reinterpret_cast<float4*>(ws + k * 320 + mat * 64 + jj) = w4;
    }
    #pragma unroll
    for (int u = 0; u < 4; u++) {
        int e0 = (u * 256 + t) * 4;
        int row = e0 >> 6, k = e0 & 63;
        int node = node0 + row;
        float4 h4 = make_float4(0.f, 0.f, 0.f, 0.f);
        if (node < NN) h4 = *reinterpret_cast<const float4*>(d_h + (size_t)node * HID + k);
        *reinterpret_cast<float4*>(hs + e0) = h4;
    }
    __syncthreads();

    int ry = t >> 5;
    int cx = t & 31;
    float acc[8][10];
    #pragma unroll
    for (int c = 0; c < 10; c++) {
        int mat = c >> 1;
        int jj = (c & 1) * 32 + cx;
        float b = bm[mat][jj];
        #pragma unroll
        for (int rr = 0; rr < 8; rr++) acc[rr][c] = b;
    }
    #pragma unroll 4
    for (int k0 = 0; k0 < 64; k0 += 4) {
        float4 hr4[8];
        #pragma unroll
        for (int rr = 0; rr < 8; rr++)
            hr4[rr] = *reinterpret_cast<const float4*>(hs + (ry * 8 + rr) * 64 + k0);
        #pragma unroll
        for (int kk = 0; kk < 4; kk++) {
            float wr[10];
            #pragma unroll
            for (int c = 0; c < 10; c++) wr[c] = ws[(k0 + kk) * 320 + cx + c * 32];
            #pragma unroll
            for (int rr = 0; rr < 8; rr++) {
                float hv = (kk == 0) ? hr4[rr].x : (kk == 1) ? hr4[rr].y
                         : (kk == 2) ? hr4[rr].z : hr4[rr].w;
                #pragma unroll
                for (int c = 0; c < 10; c++) acc[rr][c] += hv * wr[c];
            }
        }
    }
    #pragma unroll
    for (int rr = 0; rr < 8; rr++) {
        int node = node0 + ry * 8 + rr;
        if (node >= NN) continue;
        #pragma unroll
        for (int c = 0; c < 10; c++) {
            int mat = c >> 1;
            int jj = (c & 1) * 32 + cx;
            size_t off = (size_t)node * HID + jj;
            if (mat == 0)      d_qn[off] = acc[rr][c];
            else if (mat == 1) d_knh[off] = __float2half_rn(acc[rr][c]);
            else if (mat == 2) d_vnh[off] = __float2half_rn(acc[rr][c]);
            else if (mat == 3) d_sn[off] = acc[rr][c];
            else               d_qwn[off] = acc[rr][c];
        }
    }
}

// softmax body shared by the even/odd pipeline slots (identical math to round 8)
#define ATTN_BODY(CK, CV, CE, CVLD) do {                                          \
    float2 k01 = __half22float2(*reinterpret_cast<const __half2*>(&(CK).x));      \
    float2 k23 = __half22float2(*reinterpret_cast<const __half2*>(&(CK).y));      \
    float2 v01 = __half22float2(*reinterpret_cast<const __half2*>(&(CV).x));      \
    float2 v23 = __half22float2(*reinterpret_cast<const __half2*>(&(CV).y));      \
    float pp = q.x * k01.x + q.y * k01.y + q.z * k23.x + q.w * k23.y              \
             + qw.x * (CE).x + qw.y * (CE).y + qw.z * (CE).z + qw.w * (CE).w;     \
    pp += __shfl_xor_sync(0xffffffffu, pp, 1);                                    \
    pp += __shfl_xor_sync(0xffffffffu, pp, 2);                                    \
    pp = (CVLD) ? pp * 0.36067376022224085f : -1e30f;                             \
    float w;                                                                      \
    if ((CVLD) && pp > m) {                                                       \
        float sc = ex2(m - pp);                                                   \
        m = pp;                                                                   \
        den *= sc;                                                                \
        acc.x *= sc; acc.y *= sc; acc.z *= sc; acc.w *= sc;                       \
        eac.x *= sc; eac.y *= sc; eac.z *= sc; eac.w *= sc;                       \
        w = 1.0f;                                                                 \
    } else {                                                                      \
        w = ex2(pp - m);                                                          \
        w = (CVLD) ? w : 0.f;                                                     \
    }                                                                             \
    den += w;                                                                     \
    acc.x += w * v01.x; acc.y += w * v01.y; acc.z += w * v23.x; acc.w += w * v23.y;\
    eac.x += w * (CE).x; eac.y += w * (CE).y; eac.z += w * (CE).z; eac.w += w * (CE).w;\
} while (0)

// ---------------- fused attention: half-warp per edge, warp per node -------------
// lane = 16*hf + 4*head + p ; lane owns channels (4h+p)*4..+3, edge-feats p*4..+3.
// K/V gathered as fp16. Two parallel softmax streams (one per half); warp-uniform
// trip count; invalid slots clamp loads and contribute w=0.
// DEPTH-2 pipeline: two explicit buffer sets (A=even it, B=odd it), each with its
// own sedge prefetch two iterations further -> 6 outstanding loads per warp.
__global__ __launch_bounds__(256) void attn_kernel(const float* __restrict__ We,
                                                   const float* __restrict__ ea,
                                                   int layer) {
    __shared__ float WeS[16 * 68 + 4];  // skewed: [r*68 + col + (col>>4)]
    int t = threadIdx.x;
    const float* Wel = We + layer * EDGE_IN * HID;
    for (int u = t; u < EDGE_IN * HID; u += 256) {
        int r = u >> 6, col = u & 63;
        WeS[r * 68 + col + (col >> 4)] = Wel[u];
    }
    __syncthreads();

    int lane = t & 31;
    int warp = t >> 5;
    int n = blockIdx.x * 8 + warp;
    if (n >= NN) return;

    int hf = lane >> 4;
    int hl = lane & 15;
    int h = hl >> 2;
    int p = hl & 3;
    int cbs = hl * 4 + h;

    float4 q  = reinterpret_cast<const float4*>(d_qn)[n * 16 + hl];
    float4 qw = reinterpret_cast<const float4*>(d_qwn)[n * 16 + hl];

    float m = -1e30f, den = 0.f;
    float4 acc = make_float4(0.f, 0.f, 0.f, 0.f);
    float4 eac = make_float4(0.f, 0.f, 0.f, 0.f);

    int beg = d_offs[n], end = d_offs[n + 1];
    int d = end - beg;
    int itmax = (d + 1) >> 1;          // warp-uniform trip count

    const float4* ea4 = reinterpret_cast<const float4*>(ea);

    int iA = beg + hf;                 // even-iteration edge cursor
    int iB = beg + hf + 2;             // odd-iteration edge cursor
    uint2 kA, vA, kB, vB;
    float4 eA, eB;
    bool vldA = false, vldB = false, vldA2 = false, vldB2 = false;
    int2 seA2 = make_int2(0, 0), seB2 = make_int2(0, 0);
    if (itmax > 0) {
        int c = end - 1;
        vldA = (iA < end);
        int2 seA = d_sedge[vldA ? iA : c];
        kA = *reinterpret_cast<const uint2*>(d_knh + (size_t)seA.x * HID + hl * 4);
        vA = *reinterpret_cast<const uint2*>(d_vnh + (size_t)seA.x * HID + hl * 4);
        eA = ea4[seA.y * 4 + p];
        vldB = (iB < end);
        int2 seB = d_sedge[vldB ? iB : c];
        kB = *reinterpret_cast<const uint2*>(d_knh + (size_t)seB.x * HID + hl * 4);
        vB = *reinterpret_cast<const uint2*>(d_vnh + (size_t)seB.x * HID + hl * 4);
        eB = ea4[seB.y * 4 + p];
        vldA2 = (iA + 4 < end);
        seA2 = d_sedge[vldA2 ? (iA + 4) : c];
        vldB2 = (iB + 4 < end);
        seB2 = d_sedge[vldB2 ? (iB + 4) : c];
    }
    for (int it = 0; it < itmax; it += 2) {
        // ---- even iteration (buffer A) ----
        {
            uint2 ck = kA, cv = vA;
            float4 ce = eA;
            bool cvld = vldA;
            if (it + 2 < itmax) {
                kA = *reinterpret_cast<const uint2*>(d_knh + (size_t)seA2.x * HID + hl * 4);
                vA = *reinterpret_cast<const uint2*>(d_vnh + (size_t)seA2.x * HID + hl * 4);
                eA = ea4[seA2.y * 4 + p];
                vldA = vldA2;
                iA += 4;
                int i8 = iA + 4;
                vldA2 = (i8 < end);
                seA2 = d_sedge[vldA2 ? i8 : (end - 1)];
            }
            ATTN_BODY(ck, cv, ce, cvld);
        }
        // ---- odd iteration (buffer B) ----
        if (it + 1 < itmax) {
            uint2 ck = kB, cv = vB;
            float4 ce = eB;
            bool cvld = vldB;
            if (it + 3 < itmax) {
                kB = *reinterpret_cast<const uint2*>(d_knh + (size_t)seB2.x * HID + hl * 4);
                vB = *reinterpret_cast<const uint2*>(d_vnh + (size_t)seB2.x * HID + hl * 4);
                eB = ea4[seB2.y * 4 + p];
                vldB = vldB2;
                iB += 4;
                int i8 = iB + 4;
                vldB2 = (i8 < end);
                seB2 = d_sedge[vldB2 ? i8 : (end - 1)];
            }
            ATTN_BODY(ck, cv, ce, cvld);
        }
    }

    // fold edge-embedding: acc[c] += sum_r eacc[h][r] * We[r][c]   (conflict-free smem)
    float ea_arr[4] = {eac.x, eac.y, eac.z, eac.w};
    #pragma unroll
    for (int r = 0; r < 16; r++) {
        float ev = __shfl_sync(0xffffffffu, ea_arr[r & 3], (h << 2) + (r >> 2), 16);
        acc.x += ev * WeS[r * 68 + cbs + 0];
        acc.y += ev * WeS[r * 68 + cbs + 1];
        acc.z += ev * WeS[r * 68 + cbs + 2];
        acc.w += ev * WeS[r * 68 + cbs + 3];
    }

    // merge the two half-warp softmax streams
    float om  = __shfl_xor_sync(0xffffffffu, m,    16);
    float odn = __shfl_xor_sync(0xffffffffu, den,  16);
    float oax = __shfl_xor_sync(0xffffffffu, acc.x, 16);
    float oay = __shfl_xor_sync(0xffffffffu, acc.y, 16);
    float oaz = __shfl_xor_sync(0xffffffffu, acc.z, 16);
    float oaw = __shfl_xor_sync(0xffffffffu, acc.w, 16);
    float mm = fmaxf(m, om);
    float sA = ex2(m - mm), sB = ex2(om - mm);
    den = den * sA + odn * sB;
    float ox = acc.x * sA + oax * sB;
    float oy = acc.y * sA + oay * sB;
    float oz = acc.z * sA + oaz * sB;
    float ow = acc.w * sA + oaw * sB;

    if (hf == 0) {
        float inv = 1.f / (den + 1e-16f);
        float4 s4 = reinterpret_cast<const float4*>(d_sn)[n * 16 + hl];
        float4 hc = reinterpret_cast<const float4*>(d_h)[n * 16 + hl];
        hc.x += fmaxf(ox * inv + s4.x, 0.f);
        hc.y += fmaxf(oy * inv + s4.y, 0.f);
        hc.z += fmaxf(oz * inv + s4.z, 0.f);
        hc.w += fmaxf(ow * inv + s4.w, 0.f);
        reinterpret_cast<float4*>(d_h)[n * 16 + hl] = hc;
    }
}

// ---------------- fused mean pool (sorted batch) + readout MLP -------------------
__global__ __launch_bounds__(1024) void pool_mlp_kernel(const int* __restrict__ batch,
    const float* __restrict__ W1, const float* __restrict__ b1,
    const float* __restrict__ W2, const float* __restrict__ b2,
    float* __restrict__ out) {
    __shared__ float red[1024];
    __shared__ float sp[64];
    __shared__ int bnd[2];
    int g = blockIdx.x, t = threadIdx.x;
    if (t == 0) {
        int lo = 0, hi = NN;
        while (lo < hi) { int mid = (lo + hi) >> 1; if (batch[mid] < g) lo = mid + 1; else hi = mid; }
        bnd[0] = lo;
        int lo2 = lo, hi2 = NN;
        while (lo2 < hi2) { int mid = (lo2 + hi2) >> 1; if (batch[mid] < g + 1) lo2 = mid + 1; else hi2 = mid; }
        bnd[1] = lo2;
    }
    __syncthreads();
    int lo = bnd[0], hi = bnd[1];
    int ch = t & 63, rg = t >> 6;     // 16 row groups
    float a = 0.f;
    for (int nd = lo + rg; nd < hi; nd += 16) a += d_h[(size_t)nd * HID + ch];
    red[t] = a;
    __syncthreads();
    if (t < 64) {
        float s = 0.f;
        #pragma unroll
        for (int j = 0; j < 16; j++) s += red[t + 64 * j];
        sp[t] = s / fmaxf((float)(hi - lo), 1.0f);
    }
    __syncthreads();
    if (t < 32) {
        float accv = b1[t];
        #pragma unroll
        for (int k = 0; k < HID; k++) accv += sp[k] * W1[k * 32 + t];
        float v = fmaxf(accv, 0.f) * W2[t];
        #pragma unroll
        for (int o = 16; o; o >>= 1) v += __shfl_xor_sync(0xffffffffu, v, o);
        if (t == 0) out[g] = v + b2[0];
    }
}

// ---------------- launch ----------------
extern "C" void kernel_launch(void* const* d_in, const int* in_sizes, int n_in,
                              void* d_out, int out_size) {
    const float* x   = (const float*)d_in[0];
    const int*   ei  = (const int*)d_in[1];
    const float* ea  = (const float*)d_in[2];
    const int*   bat = (const int*)d_in[3];
    const float* Wn  = (const float*)d_in[4];
    const float* bn  = (const float*)d_in[5];
    const float* Wq  = (const float*)d_in[6];
    const float* bq  = (const float*)d_in[7];
    const float* Wk  = (const float*)d_in[8];
    const float* bk  = (const float*)d_in[9];
    const float* Wv  = (const float*)d_in[10];
    const float* bv  = (const float*)d_in[11];
    const float* We  = (const float*)d_in[12];
    const float* Ws  = (const float*)d_in[13];
    const float* bs  = (const float*)d_in[14];
    const float* W1  = (const float*)d_in[15];
    const float* b1  = (const float*)d_in[16];
    const float* W2  = (const float*)d_in[17];
    const float* b2  = (const float*)d_in[18];
    float* out = (float*)d_out;

    cudaFuncSetAttribute(qkvs_kernel, cudaFuncAttributeMaxDynamicSharedMemorySize, 100 * 1024);

    // 1) counting sort of edges by dst -> CSR of {src, eid}
    zero_deg_kernel<<<(NN + 255) / 256, 256>>>();
    hist_kernel<<<(EE + 255) / 256, 256>>>(ei);
    int nb = (NN + 1023) / 1024;
    scan1_kernel<<<nb, 1024>>>();
    scan3_kernel<<<(NN + 255) / 256, 256>>>(nb);
    scatter_kernel<<<(EE + 255) / 256, 256>>>(ei);

    // 2) input embedding + all-layer M precompute
    node_in_kernel<<<(NN + 3) / 4, 256>>>(x, Wn, bn);
    prep_M_kernel<<<dim3(16, NLAYER), 256>>>(Wq, bq, We);

    // 3) transformer conv layers
    for (int l = 0; l < NLAYER; l++) {
        qkvs_kernel<<<(NN + 63) / 64, 256, (64 * 64 + 64 * 320) * 4>>>(
            Wq, bq, Wk, bk, Wv, bv, Ws, bs, l);
        attn_kernel<<<(NN + 7) / 8, 256>>>(We, ea, l);
    }

    // 4) fused mean pool + MLP head (batch is sorted)
    pool_mlp_kernel<<<GG, 1024>>>(bat, W1, b1, W2, b2, out);
}

// round 10
// speedup vs baseline: 1.4990x; 1.1996x over previous
#include <cuda_runtime.h>
#include <cuda_fp16.h>
#include <math.h>

#define NN 50000
#define EE 1600000
#define GG 64
#define NODE_IN 32
#define HID 64
#define EDGE_IN 16
#define NLAYER 3

// ---------------- device scratch (static globals; no runtime alloc) ----------------
__device__ float d_h[NN * HID];
__device__ float d_qn[NN * HID];
__device__ __align__(16) __half d_knh[NN * HID];   // K in fp16 (halved gather bytes)
__device__ __align__(16) __half d_vnh[NN * HID];   // V in fp16
__device__ float d_sn[NN * HID];
__device__ float d_qwn[NN * HID];   // per-node q.We projection (4 heads x 16 r, packed)
__device__ int   d_deg[NN];
__device__ int   d_offs[NN + 1];
__device__ int   d_cursor[NN];
__device__ int   d_bsum[64];
__device__ int2  d_sedge[EE];       // {src, eid} sorted by dst
__device__ float d_M[NLAYER * HID * HID];   // fused Wq x We matrices (all layers)
__device__ float d_bqw[NLAYER * HID];

__device__ __forceinline__ float ex2(float x) {
    float r;
    asm("ex2.approx.f32 %0, %1;" : "=f"(r) : "f"(x));
    return r;
}
__device__ __forceinline__ unsigned tf32of(float x) {
    unsigned r;
    asm("cvt.rna.tf32.f32 %0, %1;" : "=r"(r) : "f"(x));
    return r;
}

// ---------------- preprocessing: counting sort of edges by dst ----------------
__global__ void zero_deg_kernel() {
    int i = blockIdx.x * blockDim.x + threadIdx.x;
    if (i < NN) d_deg[i] = 0;
}

__global__ void hist_kernel(const int* __restrict__ ei) {
    int e = blockIdx.x * blockDim.x + threadIdx.x;
    if (e < EE) atomicAdd(&d_deg[ei[EE + e]], 1);
}

__global__ void scan1_kernel() {
    __shared__ int s[1024];
    int t = threadIdx.x;
    int i = blockIdx.x * 1024 + t;
    int v = (i < NN) ? d_deg[i] : 0;
    s[t] = v;
    __syncthreads();
    for (int o = 1; o < 1024; o <<= 1) {
        int x = (t >= o) ? s[t - o] : 0;
        __syncthreads();
        s[t] += x;
        __syncthreads();
    }
    if (i < NN) d_offs[i] = s[t] - v;
    if (t == 1023) d_bsum[blockIdx.x] = s[t];
}

// scan3 folds the cross-block prefix: each block loads the <=64 block sums into
// smem and sums below its own block id.
__global__ void scan3_kernel(int nb) {
    __shared__ int pref[64];
    int t = threadIdx.x;
    if (t < nb) pref[t] = d_bsum[t];
    __syncthreads();
    int i = blockIdx.x * 256 + t;
    if (i < NN) {
        int b = i >> 10;
        int add = 0;
        for (int j = 0; j < b; j++) add += pref[j];
        int v = d_offs[i] + add;
        d_offs[i] = v;
        d_cursor[i] = v;
    }
    if (i == 0) {
        int tot = 0;
        for (int j = 0; j < nb; j++) tot += pref[j];
        d_offs[NN] = tot;   // == EE
    }
}

__global__ void scatter_kernel(const int* __restrict__ ei) {
    int e = blockIdx.x * blockDim.x + threadIdx.x;
    if (e < EE) {
        int dstv = ei[EE + e];
        int pos = atomicAdd(&d_cursor[dstv], 1);
        d_sedge[pos] = make_int2(ei[e], e);
    }
}

// ---------------- input embedding: h = relu(x @ Wn + bn) ----------------
__global__ __launch_bounds__(256) void node_in_kernel(const float* __restrict__ x,
                                                      const float* __restrict__ Wn,
                                                      const float* __restrict__ bn) {
    __shared__ float Wns[NODE_IN * HID];
    __shared__ float bns[HID];
    __shared__ float xs[4][NODE_IN];
    int t = threadIdx.x;
    for (int u = t; u < NODE_IN * HID; u += 256) Wns[u] = Wn[u];
    if (t < HID) bns[t] = bn[t];
    int j = t & 63, y = t >> 6;
    int node = blockIdx.x * 4 + y;
    if (j < NODE_IN && node < NN) xs[y][j] = x[node * NODE_IN + j];
    __syncthreads();
    if (node < NN) {
        float a = bns[j];
        #pragma unroll
        for (int k = 0; k < NODE_IN; k++) a += xs[y][k] * Wns[k * HID + j];
        d_h[(size_t)node * HID + j] = fmaxf(a, 0.f);
    }
}

// ---------------- all layers: M = per-head (Wq x We), bqw = per-head (bq x We) ----
__global__ void prep_M_kernel(const float* __restrict__ Wq, const float* __restrict__ bq,
                              const float* __restrict__ We) {
    int layer = blockIdx.y;
    int idx = blockIdx.x * 256 + threadIdx.x;
    const float* Wql = Wq + layer * HID * HID;
    const float* Wel = We + layer * EDGE_IN * HID;
    if (idx < HID * HID) {
        int krow = idx >> 6, col = idx & 63;
        int h = col >> 4, r = col & 15;
        float s = 0.f;
        #pragma unroll
        for (int c = 0; c < 16; c++)
            s += Wql[krow * HID + h * 16 + c] * Wel[r * HID + h * 16 + c];
        d_M[layer * HID * HID + idx] = s;
    }
    if (idx < HID) {
        int h = idx >> 4, r = idx & 15;
        const float* bql = bq + layer * HID;
        float s = 0.f;
        #pragma unroll
        for (int c = 0; c < 16; c++)
            s += bql[h * 16 + c] * Wel[r * HID + h * 16 + c];
        d_bqw[layer * HID + idx] = s;
    }
}

// ---------------- fused Q/K/V/Skip/QW node GEMM — tf32 tensor cores --------------
// Block: 64 nodes x 320 cols, 8 warps. Warp (rb = w>>1, cb = w&1) owns a 16x160
// slab = 20 m16n8k8 tiles x 8 k-steps. Fragments loaded from smem with the PTX
// lane mapping; strides 68 (hs) / 328 (ws) make all fragment loads conflict-free.
// K (mat 1) and V (mat 2) written as fp16; Q/S/QW stay fp32.
#define HS_STRIDE 68
#define WS_STRIDE 328
__global__ __launch_bounds__(256) void qkvs_kernel(
    const float* __restrict__ Wq, const float* __restrict__ bq,
    const float* __restrict__ Wk, const float* __restrict__ bk,
    const float* __restrict__ Wv, const float* __restrict__ bv,
    const float* __restrict__ Ws, const float* __restrict__ bs, int layer) {
    extern __shared__ float sm[];
    float* hs  = sm;                               // 64 x 68
    float* ws  = sm + 64 * HS_STRIDE;              // 64 x 328 (320 used)
    float* bss = sm + 64 * HS_STRIDE + 64 * WS_STRIDE;   // 320 bias values
    const float* Wm[5] = {Wq + layer * HID * HID, Wk + layer * HID * HID,
                          Wv + layer * HID * HID, Ws + layer * HID * HID,
                          d_M + layer * HID * HID};
    const float* bm[5] = {bq + layer * HID, bk + layer * HID, bv + layer * HID,
                          bs + layer * HID, d_bqw + layer * HID};
    int t = threadIdx.x;
    int node0 = blockIdx.x * 64;

    // weights -> smem (stride 328), coalesced float4
    #pragma unroll
    for (int u = 0; u < 20; u++) {
        int mat = u >> 2;
        int e0 = ((u & 3) * 256 + t) * 4;
        int k = e0 >> 6, jj = e0 & 63;
        float4 w4 = *reinterpret_cast<const float4*>(Wm[mat] + k * HID + jj);
        *reinterpret_cast<float4*>(ws + k * WS_STRIDE + mat * 64 + jj) = w4;
    }
    // h tile -> smem (stride 68)
    #pragma unroll
    for (int u = 0; u < 4; u++) {
        int e0 = (u * 256 + t) * 4;
        int row = e0 >> 6, k = e0 & 63;
        int node = node0 + row;
        float4 h4 = make_float4(0.f, 0.f, 0.f, 0.f);
        if (node < NN) h4 = *reinterpret_cast<const float4*>(d_h + (size_t)node * HID + k);
        *reinterpret_cast<float4*>(hs + row * HS_STRIDE + k) = h4;
    }
    // biases -> smem (col layout mat*64+jj)
    for (int u = t; u < 320; u += 256) bss[u] = bm[u >> 6][u & 63];
    __syncthreads();

    int warp = t >> 5;
    int lane = t & 31;
    int rb = warp >> 1;          // row block: rows rb*16 .. +15
    int cb = warp & 1;           // col half: cols cb*160 .. +159
    int gid = lane >> 2;         // 0..7
    int tg  = lane & 3;          // 0..3

    float c[20][4];
    #pragma unroll
    for (int nt = 0; nt < 20; nt++) {
        c[nt][0] = 0.f; c[nt][1] = 0.f; c[nt][2] = 0.f; c[nt][3] = 0.f;
    }

    #pragma unroll
    for (int ks = 0; ks < 8; ks++) {
        int k0 = ks * 8;
        // A fragment (16x8, row-major)
        const float* hb = hs + (rb * 16) * HS_STRIDE + k0;
        unsigned a0 = tf32of(hb[gid * HS_STRIDE + tg]);
        unsigned a1 = tf32of(hb[(gid + 8) * HS_STRIDE + tg]);
        unsigned a2 = tf32of(hb[gid * HS_STRIDE + tg + 4]);
        unsigned a3 = tf32of(hb[(gid + 8) * HS_STRIDE + tg + 4]);
        #pragma unroll
        for (int nt = 0; nt < 20; nt++) {
            int coln = cb * 160 + nt * 8 + gid;
            // B fragment (8x8, col-major): row = tg (+4), col = gid
            unsigned b0 = tf32of(ws[(k0 + tg) * WS_STRIDE + coln]);
            unsigned b1 = tf32of(ws[(k0 + 4 + tg) * WS_STRIDE + coln]);
            asm volatile(
                "mma.sync.aligned.m16n8k8.row.col.f32.tf32.tf32.f32 "
                "{%0,%1,%2,%3}, {%4,%5,%6,%7}, {%8,%9}, {%0,%1,%2,%3};"
                : "+f"(c[nt][0]), "+f"(c[nt][1]), "+f"(c[nt][2]), "+f"(c[nt][3])
                : "r"(a0), "r"(a1), "r"(a2), "r"(a3), "r"(b0), "r"(b1));
        }
    }

    // epilogue: add bias, store (K/V as fp16)
    int r0 = node0 + rb * 16 + gid;
    int r1 = r0 + 8;
    #pragma unroll
    for (int nt = 0; nt < 20; nt++) {
        int col = cb * 160 + nt * 8 + tg * 2;
        int mat = col >> 6, jj = col & 63;
        float b0 = bss[col], b1 = bss[col + 1];
        float v00 = c[nt][0] + b0, v01 = c[nt][1] + b1;   // row r0
        float v10 = c[nt][2] + b0, v11 = c[nt][3] + b1;   // row r1
        if (mat == 0) {
            if (r0 < NN) *reinterpret_cast<float2*>(d_qn + (size_t)r0 * HID + jj) = make_float2(v00, v01);
            if (r1 < NN) *reinterpret_cast<float2*>(d_qn + (size_t)r1 * HID + jj) = make_float2(v10, v11);
        } else if (mat == 1) {
            if (r0 < NN) *reinterpret_cast<__half2*>(d_knh + (size_t)r0 * HID + jj) = __floats2half2_rn(v00, v01);
            if (r1 < NN) *reinterpret_cast<__half2*>(d_knh + (size_t)r1 * HID + jj) = __floats2half2_rn(v10, v11);
        } else if (mat == 2) {
            if (r0 < NN) *reinterpret_cast<__half2*>(d_vnh + (size_t)r0 * HID + jj) = __floats2half2_rn(v00, v01);
            if (r1 < NN) *reinterpret_cast<__half2*>(d_vnh + (size_t)r1 * HID + jj) = __floats2half2_rn(v10, v11);
        } else if (mat == 3) {
            if (r0 < NN) *reinterpret_cast<float2*>(d_sn + (size_t)r0 * HID + jj) = make_float2(v00, v01);
            if (r1 < NN) *reinterpret_cast<float2*>(d_sn + (size_t)r1 * HID + jj) = make_float2(v10, v11);
        } else {
            if (r0 < NN) *reinterpret_cast<float2*>(d_qwn + (size_t)r0 * HID + jj) = make_float2(v00, v01);
            if (r1 < NN) *reinterpret_cast<float2*>(d_qwn + (size_t)r1 * HID + jj) = make_float2(v10, v11);
        }
    }
}
#define QKVS_SMEM ((64 * HS_STRIDE + 64 * WS_STRIDE + 320) * 4)

// softmax body shared by the even/odd pipeline slots (identical math to round 8)
#define ATTN_BODY(CK, CV, CE, CVLD) do {                                          \
    float2 k01 = __half22float2(*reinterpret_cast<const __half2*>(&(CK).x));      \
    float2 k23 = __half22float2(*reinterpret_cast<const __half2*>(&(CK).y));      \
    float2 v01 = __half22float2(*reinterpret_cast<const __half2*>(&(CV).x));      \
    float2 v23 = __half22float2(*reinterpret_cast<const __half2*>(&(CV).y));      \
    float pp = q.x * k01.x + q.y * k01.y + q.z * k23.x + q.w * k23.y              \
             + qw.x * (CE).x + qw.y * (CE).y + qw.z * (CE).z + qw.w * (CE).w;     \
    pp += __shfl_xor_sync(0xffffffffu, pp, 1);                                    \
    pp += __shfl_xor_sync(0xffffffffu, pp, 2);                                    \
    pp = (CVLD) ? pp * 0.36067376022224085f : -1e30f;                             \
    float w;                                                                      \
    if ((CVLD) && pp > m) {                                                       \
        float sc = ex2(m - pp);                                                   \
        m = pp;                                                                   \
        den *= sc;                                                                \
        acc.x *= sc; acc.y *= sc; acc.z *= sc; acc.w *= sc;                       \
        eac.x *= sc; eac.y *= sc; eac.z *= sc; eac.w *= sc;                       \
        w = 1.0f;                                                                 \
    } else {                                                                      \
        w = ex2(pp - m);                                                          \
        w = (CVLD) ? w : 0.f;                                                     \
    }                                                                             \
    den += w;                                                                     \
    acc.x += w * v01.x; acc.y += w * v01.y; acc.z += w * v23.x; acc.w += w * v23.y;\
    eac.x += w * (CE).x; eac.y += w * (CE).y; eac.z += w * (CE).z; eac.w += w * (CE).w;\
} while (0)

// ---------------- fused attention: half-warp per edge, warp per node -------------
// lane = 16*hf + 4*head + p ; lane owns channels (4h+p)*4..+3, edge-feats p*4..+3.
// K/V gathered as fp16. Two parallel softmax streams (one per half); warp-uniform
// trip count; invalid slots clamp loads and contribute w=0.
// DEPTH-2 pipeline: two explicit buffer sets (A=even it, B=odd it), each with its
// own sedge prefetch two iterations further -> 6 outstanding loads per warp.
__global__ __launch_bounds__(256) void attn_kernel(const float* __restrict__ We,
                                                   const float* __restrict__ ea,
                                                   int layer) {
    __shared__ float WeS[16 * 68 + 4];  // skewed: [r*68 + col + (col>>4)]
    int t = threadIdx.x;
    const float* Wel = We + layer * EDGE_IN * HID;
    for (int u = t; u < EDGE_IN * HID; u += 256) {
        int r = u >> 6, col = u & 63;
        WeS[r * 68 + col + (col >> 4)] = Wel[u];
    }
    __syncthreads();

    int lane = t & 31;
    int warp = t >> 5;
    int n = blockIdx.x * 8 + warp;
    if (n >= NN) return;

    int hf = lane >> 4;
    int hl = lane & 15;
    int h = hl >> 2;
    int p = hl & 3;
    int cbs = hl * 4 + h;

    float4 q  = reinterpret_cast<const float4*>(d_qn)[n * 16 + hl];
    float4 qw = reinterpret_cast<const float4*>(d_qwn)[n * 16 + hl];

    float m = -1e30f, den = 0.f;
    float4 acc = make_float4(0.f, 0.f, 0.f, 0.f);
    float4 eac = make_float4(0.f, 0.f, 0.f, 0.f);

    int beg = d_offs[n], end = d_offs[n + 1];
    int d = end - beg;
    int itmax = (d + 1) >> 1;          // warp-uniform trip count

    const float4* ea4 = reinterpret_cast<const float4*>(ea);

    int iA = beg + hf;                 // even-iteration edge cursor
    int iB = beg + hf + 2;             // odd-iteration edge cursor
    uint2 kA, vA, kB, vB;
    float4 eA, eB;
    bool vldA = false, vldB = false, vldA2 = false, vldB2 = false;
    int2 seA2 = make_int2(0, 0), seB2 = make_int2(0, 0);
    if (itmax > 0) {
        int c = end - 1;
        vldA = (iA < end);
        int2 seA = d_sedge[vldA ? iA : c];
        kA = *reinterpret_cast<const uint2*>(d_knh + (size_t)seA.x * HID + hl * 4);
        vA = *reinterpret_cast<const uint2*>(d_vnh + (size_t)seA.x * HID + hl * 4);
        eA = ea4[seA.y * 4 + p];
        vldB = (iB < end);
        int2 seB = d_sedge[vldB ? iB : c];
        kB = *reinterpret_cast<const uint2*>(d_knh + (size_t)seB.x * HID + hl * 4);
        vB = *reinterpret_cast<const uint2*>(d_vnh + (size_t)seB.x * HID + hl * 4);
        eB = ea4[seB.y * 4 + p];
        vldA2 = (iA + 4 < end);
        seA2 = d_sedge[vldA2 ? (iA + 4) : c];
        vldB2 = (iB + 4 < end);
        seB2 = d_sedge[vldB2 ? (iB + 4) : c];
    }
    for (int it = 0; it < itmax; it += 2) {
        // ---- even iteration (buffer A) ----
        {
            uint2 ck = kA, cv = vA;
            float4 ce = eA;
            bool cvld = vldA;
            if (it + 2 < itmax) {
                kA = *reinterpret_cast<const uint2*>(d_knh + (size_t)seA2.x * HID + hl * 4);
                vA = *reinterpret_cast<const uint2*>(d_vnh + (size_t)seA2.x * HID + hl * 4);
                eA = ea4[seA2.y * 4 + p];
                vldA = vldA2;
                iA += 4;
                int i8 = iA + 4;
                vldA2 = (i8 < end);
                seA2 = d_sedge[vldA2 ? i8 : (end - 1)];
            }
            ATTN_BODY(ck, cv, ce, cvld);
        }
        // ---- odd iteration (buffer B) ----
        if (it + 1 < itmax) {
            uint2 ck = kB, cv = vB;
            float4 ce = eB;
            bool cvld = vldB;
            if (it + 3 < itmax) {
                kB = *reinterpret_cast<const uint2*>(d_knh + (size_t)seB2.x * HID + hl * 4);
                vB = *reinterpret_cast<const uint2*>(d_vnh + (size_t)seB2.x * HID + hl * 4);
                eB = ea4[seB2.y * 4 + p];
                vldB = vldB2;
                iB += 4;
                int i8 = iB + 4;
                vldB2 = (i8 < end);
                seB2 = d_sedge[vldB2 ? i8 : (end - 1)];
            }
            ATTN_BODY(ck, cv, ce, cvld);
        }
    }

    // fold edge-embedding: acc[c] += sum_r eacc[h][r] * We[r][c]   (conflict-free smem)
    float ea_arr[4] = {eac.x, eac.y, eac.z, eac.w};
    #pragma unroll
    for (int r = 0; r < 16; r++) {
        float ev = __shfl_sync(0xffffffffu, ea_arr[r & 3], (h << 2) + (r >> 2), 16);
        acc.x += ev * WeS[r * 68 + cbs + 0];
        acc.y += ev * WeS[r * 68 + cbs + 1];
        acc.z += ev * WeS[r * 68 + cbs + 2];
        acc.w += ev * WeS[r * 68 + cbs + 3];
    }

    // merge the two half-warp softmax streams
    float om  = __shfl_xor_sync(0xffffffffu, m,    16);
    float odn = __shfl_xor_sync(0xffffffffu, den,  16);
    float oax = __shfl_xor_sync(0xffffffffu, acc.x, 16);
    float oay = __shfl_xor_sync(0xffffffffu, acc.y, 16);
    float oaz = __shfl_xor_sync(0xffffffffu, acc.z, 16);
    float oaw = __shfl_xor_sync(0xffffffffu, acc.w, 16);
    float mm = fmaxf(m, om);
    float sA = ex2(m - mm), sB = ex2(om - mm);
    den = den * sA + odn * sB;
    float ox = acc.x * sA + oax * sB;
    float oy = acc.y * sA + oay * sB;
    float oz = acc.z * sA + oaz * sB;
    float ow = acc.w * sA + oaw * sB;

    if (hf == 0) {
        float inv = 1.f / (den + 1e-16f);
        float4 s4 = reinterpret_cast<const float4*>(d_sn)[n * 16 + hl];
        float4 hc = reinterpret_cast<const float4*>(d_h)[n * 16 + hl];
        hc.x += fmaxf(ox * inv + s4.x, 0.f);
        hc.y += fmaxf(oy * inv + s4.y, 0.f);
        hc.z += fmaxf(oz * inv + s4.z, 0.f);
        hc.w += fmaxf(ow * inv + s4.w, 0.f);
        reinterpret_cast<float4*>(d_h)[n * 16 + hl] = hc;
    }
}

// ---------------- fused mean pool (sorted batch) + readout MLP -------------------
__global__ __launch_bounds__(1024) void pool_mlp_kernel(const int* __restrict__ batch,
    const float* __restrict__ W1, const float* __restrict__ b1,
    const float* __restrict__ W2, const float* __restrict__ b2,
    float* __restrict__ out) {
    __shared__ float red[1024];
    __shared__ float sp[64];
    __shared__ int bnd[2];
    int g = blockIdx.x, t = threadIdx.x;
    if (t == 0) {
        int lo = 0, hi = NN;
        while (lo < hi) { int mid = (lo + hi) >> 1; if (batch[mid] < g) lo = mid + 1; else hi = mid; }
        bnd[0] = lo;
        int lo2 = lo, hi2 = NN;
        while (lo2 < hi2) { int mid = (lo2 + hi2) >> 1; if (batch[mid] < g + 1) lo2 = mid + 1; else hi2 = mid; }
        bnd[1] = lo2;
    }
    __syncthreads();
    int lo = bnd[0], hi = bnd[1];
    int ch = t & 63, rg = t >> 6;     // 16 row groups
    float a = 0.f;
    for (int nd = lo + rg; nd < hi; nd += 16) a += d_h[(size_t)nd * HID + ch];
    red[t] = a;
    __syncthreads();
    if (t < 64) {
        float s = 0.f;
        #pragma unroll
        for (int j = 0; j < 16; j++) s += red[t + 64 * j];
        sp[t] = s / fmaxf((float)(hi - lo), 1.0f);
    }
    __syncthreads();
    if (t < 32) {
        float accv = b1[t];
        #pragma unroll
        for (int k = 0; k < HID; k++) accv += sp[k] * W1[k * 32 + t];
        float v = fmaxf(accv, 0.f) * W2[t];
        #pragma unroll
        for (int o = 16; o; o >>= 1) v += __shfl_xor_sync(0xffffffffu, v, o);
        if (t == 0) out[g] = v + b2[0];
    }
}

// ---------------- launch ----------------
extern "C" void kernel_launch(void* const* d_in, const int* in_sizes, int n_in,
                              void* d_out, int out_size) {
    const float* x   = (const float*)d_in[0];
    const int*   ei  = (const int*)d_in[1];
    const float* ea  = (const float*)d_in[2];
    const int*   bat = (const int*)d_in[3];
    const float* Wn  = (const float*)d_in[4];
    const float* bn  = (const float*)d_in[5];
    const float* Wq  = (const float*)d_in[6];
    const float* bq  = (const float*)d_in[7];
    const float* Wk  = (const float*)d_in[8];
    const float* bk  = (const float*)d_in[9];
    const float* Wv  = (const float*)d_in[10];
    const float* bv  = (const float*)d_in[11];
    const float* We  = (const float*)d_in[12];
    const float* Ws  = (const float*)d_in[13];
    const float* bs  = (const float*)d_in[14];
    const float* W1  = (const float*)d_in[15];
    const float* b1  = (const float*)d_in[16];
    const float* W2  = (const float*)d_in[17];
    const float* b2  = (const float*)d_in[18];
    float* out = (float*)d_out;

    cudaFuncSetAttribute(qkvs_kernel, cudaFuncAttributeMaxDynamicSharedMemorySize, 108 * 1024);

    // 1) counting sort of edges by dst -> CSR of {src, eid}
    zero_deg_kernel<<<(NN + 255) / 256, 256>>>();
    hist_kernel<<<(EE + 255) / 256, 256>>>(ei);
    int nb = (NN + 1023) / 1024;
    scan1_kernel<<<nb, 1024>>>();
    scan3_kernel<<<(NN + 255) / 256, 256>>>(nb);
    scatter_kernel<<<(EE + 255) / 256, 256>>>(ei);

    // 2) input embedding + all-layer M precompute
    node_in_kernel<<<(NN + 3) / 4, 256>>>(x, Wn, bn);
    prep_M_kernel<<<dim3(16, NLAYER), 256>>>(Wq, bq, We);

    // 3) transformer conv layers
    for (int l = 0; l < NLAYER; l++) {
        qkvs_kernel<<<(NN + 63) / 64, 256, QKVS_SMEM>>>(
            Wq, bq, Wk, bk, Wv, bv, Ws, bs, l);
        attn_kernel<<<(NN + 7) / 8, 256>>>(We, ea, l);
    }

    // 4) fused mean pool + MLP head (batch is sorted)
    pool_mlp_kernel<<<GG, 1024>>>(bat, W1, b1, W2, b2, out);
}

// round 11
// speedup vs baseline: 1.5141x; 1.0101x over previous
#include <cuda_runtime.h>
#include <cuda_fp16.h>
#include <math.h>

#define NN 50000
#define EE 1600000
#define GG 64
#define NODE_IN 32
#define HID 64
#define EDGE_IN 16
#define NLAYER 3

// ---------------- device scratch (static globals; no runtime alloc) ----------------
__device__ float d_h[NN * HID];
__device__ float d_qn[NN * HID];
__device__ __align__(16) __half d_kvh[NN * 128];   // interleaved K|V fp16: lane hl -> [K4|V4]
__device__ float d_sn[NN * HID];
__device__ float d_qwn[NN * HID];   // per-node q.We projection (4 heads x 16 r, packed)
__device__ int   d_deg[NN];
__device__ int   d_offs[NN + 1];
__device__ int   d_cursor[NN];
__device__ int   d_bsum[64];
__device__ int   d_ssrc[EE];        // src sorted by dst (4B loads in attn loop)
__device__ int   d_seid[EE];        // original eid sorted by dst (permute only)
__device__ __align__(16) __half d_seah[(size_t)EE * EDGE_IN];  // fp16 permuted edge_attr
__device__ float d_M[NLAYER * HID * HID];   // fused Wq x We matrices (all layers)
__device__ float d_bqw[NLAYER * HID];

__device__ __forceinline__ float ex2(float x) {
    float r;
    asm("ex2.approx.f32 %0, %1;" : "=f"(r) : "f"(x));
    return r;
}
__device__ __forceinline__ unsigned tf32of(float x) {
    unsigned r;
    asm("cvt.rna.tf32.f32 %0, %1;" : "=r"(r) : "f"(x));
    return r;
}

// ---------------- preprocessing: counting sort of edges by dst ----------------
__global__ void zero_deg_kernel() {
    int i = blockIdx.x * blockDim.x + threadIdx.x;
    if (i < NN) d_deg[i] = 0;
}

__global__ void hist_kernel(const int* __restrict__ ei) {
    int e = blockIdx.x * blockDim.x + threadIdx.x;
    if (e < EE) atomicAdd(&d_deg[ei[EE + e]], 1);
}

__global__ void scan1_kernel() {
    __shared__ int s[1024];
    int t = threadIdx.x;
    int i = blockIdx.x * 1024 + t;
    int v = (i < NN) ? d_deg[i] : 0;
    s[t] = v;
    __syncthreads();
    for (int o = 1; o < 1024; o <<= 1) {
        int x = (t >= o) ? s[t - o] : 0;
        __syncthreads();
        s[t] += x;
        __syncthreads();
    }
    if (i < NN) d_offs[i] = s[t] - v;
    if (t == 1023) d_bsum[blockIdx.x] = s[t];
}

// scan3 folds the cross-block prefix: each block loads the <=64 block sums into
// smem and sums below its own block id.
__global__ void scan3_kernel(int nb) {
    __shared__ int pref[64];
    int t = threadIdx.x;
    if (t < nb) pref[t] = d_bsum[t];
    __syncthreads();
    int i = blockIdx.x * 256 + t;
    if (i < NN) {
        int b = i >> 10;
        int add = 0;
        for (int j = 0; j < b; j++) add += pref[j];
        int v = d_offs[i] + add;
        d_offs[i] = v;
        d_cursor[i] = v;
    }
    if (i == 0) {
        int tot = 0;
        for (int j = 0; j < nb; j++) tot += pref[j];
        d_offs[NN] = tot;   // == EE
    }
}

__global__ void scatter_kernel(const int* __restrict__ ei) {
    int e = blockIdx.x * blockDim.x + threadIdx.x;
    if (e < EE) {
        int dstv = ei[EE + e];
        int pos = atomicAdd(&d_cursor[dstv], 1);
        d_ssrc[pos] = ei[e];
        d_seid[pos] = e;
    }
}

// permute edge_attr into sorted-edge order, fp16 (51MB, L2-resident across layers)
__global__ void permute_eah_kernel(const float* __restrict__ ea) {
    int t = blockIdx.x * blockDim.x + threadIdx.x;
    if (t < EE * 4) {
        int pos = t >> 2;
        int u = t & 3;
        int eid = d_seid[pos];
        float4 v = reinterpret_cast<const float4*>(ea)[(size_t)eid * 4 + u];
        __half2 h0 = __floats2half2_rn(v.x, v.y);
        __half2 h1 = __floats2half2_rn(v.z, v.w);
        __half2* dst = reinterpret_cast<__half2*>(d_seah + (size_t)pos * 16 + u * 4);
        dst[0] = h0;
        dst[1] = h1;
    }
}

// ---------------- input embedding: h = relu(x @ Wn + bn) ----------------
__global__ __launch_bounds__(256) void node_in_kernel(const float* __restrict__ x,
                                                      const float* __restrict__ Wn,
                                                      const float* __restrict__ bn) {
    __shared__ float Wns[NODE_IN * HID];
    __shared__ float bns[HID];
    __shared__ float xs[4][NODE_IN];
    int t = threadIdx.x;
    for (int u = t; u < NODE_IN * HID; u += 256) Wns[u] = Wn[u];
    if (t < HID) bns[t] = bn[t];
    int j = t & 63, y = t >> 6;
    int node = blockIdx.x * 4 + y;
    if (j < NODE_IN && node < NN) xs[y][j] = x[node * NODE_IN + j];
    __syncthreads();
    if (node < NN) {
        float a = bns[j];
        #pragma unroll
        for (int k = 0; k < NODE_IN; k++) a += xs[y][k] * Wns[k * HID + j];
        d_h[(size_t)node * HID + j] = fmaxf(a, 0.f);
    }
}

// ---------------- all layers: M = per-head (Wq x We), bqw = per-head (bq x We) ----
__global__ void prep_M_kernel(const float* __restrict__ Wq, const float* __restrict__ bq,
                              const float* __restrict__ We) {
    int layer = blockIdx.y;
    int idx = blockIdx.x * 256 + threadIdx.x;
    const float* Wql = Wq + layer * HID * HID;
    const float* Wel = We + layer * EDGE_IN * HID;
    if (idx < HID * HID) {
        int krow = idx >> 6, col = idx & 63;
        int h = col >> 4, r = col & 15;
        float s = 0.f;
        #pragma unroll
        for (int c = 0; c < 16; c++)
            s += Wql[krow * HID + h * 16 + c] * Wel[r * HID + h * 16 + c];
        d_M[layer * HID * HID + idx] = s;
    }
    if (idx < HID) {
        int h = idx >> 4, r = idx & 15;
        const float* bql = bq + layer * HID;
        float s = 0.f;
        #pragma unroll
        for (int c = 0; c < 16; c++)
            s += bql[h * 16 + c] * Wel[r * HID + h * 16 + c];
        d_bqw[layer * HID + idx] = s;
    }
}

// ---------------- fused Q/K/V/Skip/QW node GEMM — tf32 tensor cores --------------
// Block: 64 nodes x 320 cols, 8 warps. Warp (rb = w>>1, cb = w&1) owns a 16x160
// slab = 20 m16n8k8 tiles x 8 k-steps. Strides 68 (hs) / 328 (ws) keep all
// fragment loads conflict-free. K (mat 1) / V (mat 2) -> interleaved fp16 d_kvh.
#define HS_STRIDE 68
#define WS_STRIDE 328
__global__ __launch_bounds__(256) void qkvs_kernel(
    const float* __restrict__ Wq, const float* __restrict__ bq,
    const float* __restrict__ Wk, const float* __restrict__ bk,
    const float* __restrict__ Wv, const float* __restrict__ bv,
    const float* __restrict__ Ws, const float* __restrict__ bs, int layer) {
    extern __shared__ float sm[];
    float* hs  = sm;                               // 64 x 68
    float* ws  = sm + 64 * HS_STRIDE;              // 64 x 328 (320 used)
    float* bss = sm + 64 * HS_STRIDE + 64 * WS_STRIDE;   // 320 bias values
    const float* Wm[5] = {Wq + layer * HID * HID, Wk + layer * HID * HID,
                          Wv + layer * HID * HID, Ws + layer * HID * HID,
                          d_M + layer * HID * HID};
    const float* bm[5] = {bq + layer * HID, bk + layer * HID, bv + layer * HID,
                          bs + layer * HID, d_bqw + layer * HID};
    int t = threadIdx.x;
    int node0 = blockIdx.x * 64;

    // weights -> smem (stride 328), coalesced float4
    #pragma unroll
    for (int u = 0; u < 20; u++) {
        int mat = u >> 2;
        int e0 = ((u & 3) * 256 + t) * 4;
        int k = e0 >> 6, jj = e0 & 63;
        float4 w4 = *reinterpret_cast<const float4*>(Wm[mat] + k * HID + jj);
        *reinterpret_cast<float4*>(ws + k * WS_STRIDE + mat * 64 + jj) = w4;
    }
    // h tile -> smem (stride 68)
    #pragma unroll
    for (int u = 0; u < 4; u++) {
        int e0 = (u * 256 + t) * 4;
        int row = e0 >> 6, k = e0 & 63;
        int node = node0 + row;
        float4 h4 = make_float4(0.f, 0.f, 0.f, 0.f);
        if (node < NN) h4 = *reinterpret_cast<const float4*>(d_h + (size_t)node * HID + k);
        *reinterpret_cast<float4*>(hs + row * HS_STRIDE + k) = h4;
    }
    // biases -> smem (col layout mat*64+jj)
    for (int u = t; u < 320; u += 256) bss[u] = bm[u >> 6][u & 63];
    __syncthreads();

    int warp = t >> 5;
    int lane = t & 31;
    int rb = warp >> 1;          // row block: rows rb*16 .. +15
    int cb = warp & 1;           // col half: cols cb*160 .. +159
    int gid = lane >> 2;         // 0..7
    int tg  = lane & 3;          // 0..3

    float c[20][4];
    #pragma unroll
    for (int nt = 0; nt < 20; nt++) {
        c[nt][0] = 0.f; c[nt][1] = 0.f; c[nt][2] = 0.f; c[nt][3] = 0.f;
    }

    #pragma unroll
    for (int ks = 0; ks < 8; ks++) {
        int k0 = ks * 8;
        const float* hb = hs + (rb * 16) * HS_STRIDE + k0;
        unsigned a0 = tf32of(hb[gid * HS_STRIDE + tg]);
        unsigned a1 = tf32of(hb[(gid + 8) * HS_STRIDE + tg]);
        unsigned a2 = tf32of(hb[gid * HS_STRIDE + tg + 4]);
        unsigned a3 = tf32of(hb[(gid + 8) * HS_STRIDE + tg + 4]);
        #pragma unroll
        for (int nt = 0; nt < 20; nt++) {
            int coln = cb * 160 + nt * 8 + gid;
            unsigned b0 = tf32of(ws[(k0 + tg) * WS_STRIDE + coln]);
            unsigned b1 = tf32of(ws[(k0 + 4 + tg) * WS_STRIDE + coln]);
            asm volatile(
                "mma.sync.aligned.m16n8k8.row.col.f32.tf32.tf32.f32 "
                "{%0,%1,%2,%3}, {%4,%5,%6,%7}, {%8,%9}, {%0,%1,%2,%3};"
                : "+f"(c[nt][0]), "+f"(c[nt][1]), "+f"(c[nt][2]), "+f"(c[nt][3])
                : "r"(a0), "r"(a1), "r"(a2), "r"(a3), "r"(b0), "r"(b1));
        }
    }

    // epilogue: add bias, store. K/V go interleaved fp16 into d_kvh:
    //   channel jj of K -> d_kvh[node*128 + (jj>>2)*8 + (jj&3)]; V same +4.
    int r0 = node0 + rb * 16 + gid;
    int r1 = r0 + 8;
    #pragma unroll
    for (int nt = 0; nt < 20; nt++) {
        int col = cb * 160 + nt * 8 + tg * 2;
        int mat = col >> 6, jj = col & 63;
        float b0 = bss[col], b1 = bss[col + 1];
        float v00 = c[nt][0] + b0, v01 = c[nt][1] + b1;   // row r0
        float v10 = c[nt][2] + b0, v11 = c[nt][3] + b1;   // row r1
        if (mat == 0) {
            if (r0 < NN) *reinterpret_cast<float2*>(d_qn + (size_t)r0 * HID + jj) = make_float2(v00, v01);
            if (r1 < NN) *reinterpret_cast<float2*>(d_qn + (size_t)r1 * HID + jj) = make_float2(v10, v11);
        } else if (mat == 1) {
            int koff = (jj >> 2) * 8 + (jj & 3);
            if (r0 < NN) *reinterpret_cast<__half2*>(d_kvh + (size_t)r0 * 128 + koff) = __floats2half2_rn(v00, v01);
            if (r1 < NN) *reinterpret_cast<__half2*>(d_kvh + (size_t)r1 * 128 + koff) = __floats2half2_rn(v10, v11);
        } else if (mat == 2) {
            int voff = (jj >> 2) * 8 + 4 + (jj & 3);
            if (r0 < NN) *reinterpret_cast<__half2*>(d_kvh + (size_t)r0 * 128 + voff) = __floats2half2_rn(v00, v01);
            if (r1 < NN) *reinterpret_cast<__half2*>(d_kvh + (size_t)r1 * 128 + voff) = __floats2half2_rn(v10, v11);
        } else if (mat == 3) {
            if (r0 < NN) *reinterpret_cast<float2*>(d_sn + (size_t)r0 * HID + jj) = make_float2(v00, v01);
            if (r1 < NN) *reinterpret_cast<float2*>(d_sn + (size_t)r1 * HID + jj) = make_float2(v10, v11);
        } else {
            if (r0 < NN) *reinterpret_cast<float2*>(d_qwn + (size_t)r0 * HID + jj) = make_float2(v00, v01);
            if (r1 < NN) *reinterpret_cast<float2*>(d_qwn + (size_t)r1 * HID + jj) = make_float2(v10, v11);
        }
    }
}
#define QKVS_SMEM ((64 * HS_STRIDE + 64 * WS_STRIDE + 320) * 4)

// softmax body (identical math to round 9/10); CKV = uint4 (K4|V4 halves),
// CE = uint2 (4 ea halves)
#define ATTN_BODY(CKV, CE, CVLD) do {                                             \
    float2 k01 = __half22float2(*reinterpret_cast<const __half2*>(&(CKV).x));     \
    float2 k23 = __half22float2(*reinterpret_cast<const __half2*>(&(CKV).y));     \
    float2 v01 = __half22float2(*reinterpret_cast<const __half2*>(&(CKV).z));     \
    float2 v23 = __half22float2(*reinterpret_cast<const __half2*>(&(CKV).w));     \
    float2 e01 = __half22float2(*reinterpret_cast<const __half2*>(&(CE).x));      \
    float2 e23 = __half22float2(*reinterpret_cast<const __half2*>(&(CE).y));      \
    float pp = q.x * k01.x + q.y * k01.y + q.z * k23.x + q.w * k23.y              \
             + qw.x * e01.x + qw.y * e01.y + qw.z * e23.x + qw.w * e23.y;         \
    pp += __shfl_xor_sync(0xffffffffu, pp, 1);                                    \
    pp += __shfl_xor_sync(0xffffffffu, pp, 2);                                    \
    pp = (CVLD) ? pp * 0.36067376022224085f : -1e30f;                             \
    float w;                                                                      \
    if ((CVLD) && pp > m) {                                                       \
        float sc = ex2(m - pp);                                                   \
        m = pp;                                                                   \
        den *= sc;                                                                \
        acc.x *= sc; acc.y *= sc; acc.z *= sc; acc.w *= sc;                       \
        eac.x *= sc; eac.y *= sc; eac.z *= sc; eac.w *= sc;                       \
        w = 1.0f;                                                                 \
    } else {                                                                      \
        w = ex2(pp - m);                                                          \
        w = (CVLD) ? w : 0.f;                                                     \
    }                                                                             \
    den += w;                                                                     \
    acc.x += w * v01.x; acc.y += w * v01.y; acc.z += w * v23.x; acc.w += w * v23.y;\
    eac.x += w * e01.x; eac.y += w * e01.y; eac.z += w * e23.x; eac.w += w * e23.y;\
} while (0)

// ---------------- fused attention: half-warp per edge, warp per node -------------
// lane = 16*hf + 4*head + p ; lane owns channels (4h+p)*4..+3, edge-feats p*4..+3.
// KV gathered as one uint4 (interleaved fp16); ea read sequentially from the
// fp16 permuted copy (coalesced). Two softmax streams; warp-uniform trip count;
// invalid slots clamp loads and contribute w=0. DEPTH-2 pipeline (A/B buffers),
// d_ssrc prefetched two iterations further.
__global__ __launch_bounds__(256) void attn_kernel(const float* __restrict__ We,
                                                   int layer) {
    __shared__ float WeS[16 * 68 + 4];  // skewed: [r*68 + col + (col>>4)]
    int t = threadIdx.x;
    const float* Wel = We + layer * EDGE_IN * HID;
    for (int u = t; u < EDGE_IN * HID; u += 256) {
        int r = u >> 6, col = u & 63;
        WeS[r * 68 + col + (col >> 4)] = Wel[u];
    }
    __syncthreads();

    int lane = t & 31;
    int warp = t >> 5;
    int n = blockIdx.x * 8 + warp;
    if (n >= NN) return;

    int hf = lane >> 4;
    int hl = lane & 15;
    int h = hl >> 2;
    int p = hl & 3;
    int cbs = hl * 4 + h;

    float4 q  = reinterpret_cast<const float4*>(d_qn)[n * 16 + hl];
    float4 qw = reinterpret_cast<const float4*>(d_qwn)[n * 16 + hl];

    float m = -1e30f, den = 0.f;
    float4 acc = make_float4(0.f, 0.f, 0.f, 0.f);
    float4 eac = make_float4(0.f, 0.f, 0.f, 0.f);

    int beg = d_offs[n], end = d_offs[n + 1];
    int d = end - beg;
    int itmax = (d + 1) >> 1;          // warp-uniform trip count

    int iA = beg + hf;                 // even-iteration edge cursor
    int iB = beg + hf + 2;             // odd-iteration edge cursor
    uint4 kvA, kvB;
    uint2 eA, eB;
    bool vldA = false, vldB = false, vldA2 = false, vldB2 = false;
    int srcA2 = 0, posA2 = 0, srcB2 = 0, posB2 = 0;
    if (itmax > 0) {
        int c = end - 1;
        vldA = (iA < end);
        int posA = vldA ? iA : c;
        int srcA = d_ssrc[posA];
        kvA = *reinterpret_cast<const uint4*>(d_kvh + (size_t)srcA * 128 + hl * 8);
        eA  = *reinterpret_cast<const uint2*>(d_seah + (size_t)posA * 16 + p * 4);
        vldB = (iB < end);
        int posB = vldB ? iB : c;
        int srcB = d_ssrc[posB];
        kvB = *reinterpret_cast<const uint4*>(d_kvh + (size_t)srcB * 128 + hl * 8);
        eB  = *reinterpret_cast<const uint2*>(d_seah + (size_t)posB * 16 + p * 4);
        vldA2 = (iA + 4 < end);
        posA2 = vldA2 ? (iA + 4) : c;
        srcA2 = d_ssrc[posA2];
        vldB2 = (iB + 4 < end);
        posB2 = vldB2 ? (iB + 4) : c;
        srcB2 = d_ssrc[posB2];
    }
    for (int it = 0; it < itmax; it += 2) {
        // ---- even iteration (buffer A) ----
        {
            uint4 ckv = kvA;
            uint2 ce = eA;
            bool cvld = vldA;
            if (it + 2 < itmax) {
                kvA = *reinterpret_cast<const uint4*>(d_kvh + (size_t)srcA2 * 128 + hl * 8);
                eA  = *reinterpret_cast<const uint2*>(d_seah + (size_t)posA2 * 16 + p * 4);
                vldA = vldA2;
                iA += 4;
                int i8 = iA + 4;
                vldA2 = (i8 < end);
                posA2 = vldA2 ? i8 : (end - 1);
                srcA2 = d_ssrc[posA2];
            }
            ATTN_BODY(ckv, ce, cvld);
        }
        // ---- odd iteration (buffer B) ----
        if (it + 1 < itmax) {
            uint4 ckv = kvB;
            uint2 ce = eB;
            bool cvld = vldB;
            if (it + 3 < itmax) {
                kvB = *reinterpret_cast<const uint4*>(d_kvh + (size_t)srcB2 * 128 + hl * 8);
                eB  = *reinterpret_cast<const uint2*>(d_seah + (size_t)posB2 * 16 + p * 4);
                vldB = vldB2;
                iB += 4;
                int i8 = iB + 4;
                vldB2 = (i8 < end);
                posB2 = vldB2 ? i8 : (end - 1);
                srcB2 = d_ssrc[posB2];
            }
            ATTN_BODY(ckv, ce, cvld);
        }
    }

    // fold edge-embedding: acc[c] += sum_r eacc[h][r] * We[r][c]   (conflict-free smem)
    float ea_arr[4] = {eac.x, eac.y, eac.z, eac.w};
    #pragma unroll
    for (int r = 0; r < 16; r++) {
        float ev = __shfl_sync(0xffffffffu, ea_arr[r & 3], (h << 2) + (r >> 2), 16);
        acc.x += ev * WeS[r * 68 + cbs + 0];
        acc.y += ev * WeS[r * 68 + cbs + 1];
        acc.z += ev * WeS[r * 68 + cbs + 2];
        acc.w += ev * WeS[r * 68 + cbs + 3];
    }

    // merge the two half-warp softmax streams
    float om  = __shfl_xor_sync(0xffffffffu, m,    16);
    float odn = __shfl_xor_sync(0xffffffffu, den,  16);
    float oax = __shfl_xor_sync(0xffffffffu, acc.x, 16);
    float oay = __shfl_xor_sync(0xffffffffu, acc.y, 16);
    float oaz = __shfl_xor_sync(0xffffffffu, acc.z, 16);
    float oaw = __shfl_xor_sync(0xffffffffu, acc.w, 16);
    float mm = fmaxf(m, om);
    float sA = ex2(m - mm), sB = ex2(om - mm);
    den = den * sA + odn * sB;
    float ox = acc.x * sA + oax * sB;
    float oy = acc.y * sA + oay * sB;
    float oz = acc.z * sA + oaz * sB;
    float ow = acc.w * sA + oaw * sB;

    if (hf == 0) {
        float inv = 1.f / (den + 1e-16f);
        float4 s4 = reinterpret_cast<const float4*>(d_sn)[n * 16 + hl];
        float4 hc = reinterpret_cast<const float4*>(d_h)[n * 16 + hl];
        hc.x += fmaxf(ox * inv + s4.x, 0.f);
        hc.y += fmaxf(oy * inv + s4.y, 0.f);
        hc.z += fmaxf(oz * inv + s4.z, 0.f);
        hc.w += fmaxf(ow * inv + s4.w, 0.f);
        reinterpret_cast<float4*>(d_h)[n * 16 + hl] = hc;
    }
}

// ---------------- fused mean pool (sorted batch) + readout MLP -------------------
__global__ __launch_bounds__(1024) void pool_mlp_kernel(const int* __restrict__ batch,
    const float* __restrict__ W1, const float* __restrict__ b1,
    const float* __restrict__ W2, const float* __restrict__ b2,
    float* __restrict__ out) {
    __shared__ float red[1024];
    __shared__ float sp[64];
    __shared__ int bnd[2];
    int g = blockIdx.x, t = threadIdx.x;
    if (t == 0) {
        int lo = 0, hi = NN;
        while (lo < hi) { int mid = (lo + hi) >> 1; if (batch[mid] < g) lo = mid + 1; else hi = mid; }
        bnd[0] = lo;
        int lo2 = lo, hi2 = NN;
        while (lo2 < hi2) { int mid = (lo2 + hi2) >> 1; if (batch[mid] < g + 1) lo2 = mid + 1; else hi2 = mid; }
        bnd[1] = lo2;
    }
    __syncthreads();
    int lo = bnd[0], hi = bnd[1];
    int ch = t & 63, rg = t >> 6;     // 16 row groups
    float a = 0.f;
    for (int nd = lo + rg; nd < hi; nd += 16) a += d_h[(size_t)nd * HID + ch];
    red[t] = a;
    __syncthreads();
    if (t < 64) {
        float s = 0.f;
        #pragma unroll
        for (int j = 0; j < 16; j++) s += red[t + 64 * j];
        sp[t] = s / fmaxf((float)(hi - lo), 1.0f);
    }
    __syncthreads();
    if (t < 32) {
        float accv = b1[t];
        #pragma unroll
        for (int k = 0; k < HID; k++) accv += sp[k] * W1[k * 32 + t];
        float v = fmaxf(accv, 0.f) * W2[t];
        #pragma unroll
        for (int o = 16; o; o >>= 1) v += __shfl_xor_sync(0xffffffffu, v, o);
        if (t == 0) out[g] = v + b2[0];
    }
}

// ---------------- launch ----------------
extern "C" void kernel_launch(void* const* d_in, const int* in_sizes, int n_in,
                              void* d_out, int out_size) {
    const float* x   = (const float*)d_in[0];
    const int*   ei  = (const int*)d_in[1];
    const float* ea  = (const float*)d_in[2];
    const int*   bat = (const int*)d_in[3];
    const float* Wn  = (const float*)d_in[4];
    const float* bn  = (const float*)d_in[5];
    const float* Wq  = (const float*)d_in[6];
    const float* bq  = (const float*)d_in[7];
    const float* Wk  = (const float*)d_in[8];
    const float* bk  = (const float*)d_in[9];
    const float* Wv  = (const float*)d_in[10];
    const float* bv  = (const float*)d_in[11];
    const float* We  = (const float*)d_in[12];
    const float* Ws  = (const float*)d_in[13];
    const float* bs  = (const float*)d_in[14];
    const float* W1  = (const float*)d_in[15];
    const float* b1  = (const float*)d_in[16];
    const float* W2  = (const float*)d_in[17];
    const float* b2  = (const float*)d_in[18];
    float* out = (float*)d_out;

    cudaFuncSetAttribute(qkvs_kernel, cudaFuncAttributeMaxDynamicSharedMemorySize, 108 * 1024);

    // 1) counting sort of edges by dst -> CSR of src/eid + fp16 permuted edge_attr
    zero_deg_kernel<<<(NN + 255) / 256, 256>>>();
    hist_kernel<<<(EE + 255) / 256, 256>>>(ei);
    int nb = (NN + 1023) / 1024;
    scan1_kernel<<<nb, 1024>>>();
    scan3_kernel<<<(NN + 255) / 256, 256>>>(nb);
    scatter_kernel<<<(EE + 255) / 256, 256>>>(ei);
    permute_eah_kernel<<<(EE * 4 + 255) / 256, 256>>>(ea);

    // 2) input embedding + all-layer M precompute
    node_in_kernel<<<(NN + 3) / 4, 256>>>(x, Wn, bn);
    prep_M_kernel<<<dim3(16, NLAYER), 256>>>(Wq, bq, We);

    // 3) transformer conv layers
    for (int l = 0; l < NLAYER; l++) {
        qkvs_kernel<<<(NN + 63) / 64, 256, QKVS_SMEM>>>(
            Wq, bq, Wk, bk, Wv, bv, Ws, bs, l);
        attn_kernel<<<(NN + 7) / 8, 256>>>(We, l);
    }

    // 4) fused mean pool + MLP head (batch is sorted)
    pool_mlp_kernel<<<GG, 1024>>>(bat, W1, b1, W2, b2, out);
}